// round 9
// baseline (speedup 1.0000x reference)
#include <cuda_runtime.h>
#include <cuda_bf16.h>
#include <cstdint>

typedef unsigned long long ull;

#define BB 64
#define NN 1700
#define CC 256
#define MAXE 16384
#define MTOT (BB*NN)
#define MTILES (MTOT/128)          // 850
#define NHT (MTILES*2)             // 1700 half-tiles (128x128)
#define NSM 148

// ---------------- scratch (device globals; no allocation allowed) ----------------
__device__ float g_h[(size_t)BB*NN*CC];            // GEMM output (fp32)
__device__ char  g_a8h[(size_t)MTOT*CC];           // A hi digit image (int8, chunked+swizzled)
__device__ char  g_a8l[(size_t)MTOT*CC];           // A lo digit image
__device__ char  g_b8h[3*65536];                   // B hi images per layer
__device__ char  g_b8l[3*65536];                   // B lo images per layer
__device__ float g_qa[MTOT];                       // A row inv-scales (rowmax/127)
__device__ float g_qb[3*256];                      // B col inv-scales
__device__ int   g_ptr[2*(NN+1)];
__device__ float g_dinv[2*NN];
__device__ int   g_esrc[2*MAXE];
__device__ float g_enorm[2*MAXE];

// ---------------- PTX helpers (all sm_80-class: valid for compute_103) ----------------
__device__ __forceinline__ uint32_t smem_u32(const void* p) {
    uint32_t a;
    asm("{ .reg .u64 t; cvta.to.shared.u64 t, %1; cvt.u32.u64 %0, t; }" : "=r"(a) : "l"(p));
    return a;
}
#define LDSM4(r0,r1,r2,r3,addr) \
    asm volatile("ldmatrix.sync.aligned.m8n8.x4.shared.b16 {%0,%1,%2,%3}, [%4];" \
        : "=r"(r0),"=r"(r1),"=r"(r2),"=r"(r3) : "r"(addr))
#define IMMA(d, a, b0, b1) \
    asm volatile("mma.sync.aligned.m16n8k32.row.col.s32.s8.s8.s32 " \
        "{%0,%1,%2,%3},{%4,%5,%6,%7},{%8,%9},{%0,%1,%2,%3};" \
        : "+r"((d)[0]),"+r"((d)[1]),"+r"((d)[2]),"+r"((d)[3]) \
        : "r"((a)[0]),"r"((a)[1]),"r"((a)[2]),"r"((a)[3]), "r"(b0),"r"(b1))
#define CPASYNC16(dst, src) \
    asm volatile("cp.async.cg.shared.global [%0], [%1], 16;" :: "r"(dst), "l"(src))
#define CPCOMMIT() asm volatile("cp.async.commit_group;")
#define CPWAIT(n)  asm volatile("cp.async.wait_group %0;" :: "n"(n))

// image element byte offset within a 128x64B block, 16B-chunk XOR swizzle
__device__ __forceinline__ uint32_t swz8(int r, int kin) {
    return (uint32_t)(r*64 + ((((kin>>4) ^ ((r>>1)&3)))<<4) + (kin&15));
}

// ---------------- fused prep: histogram -> scan -> dinv -> CSR fill, both edge sets ----------------
__global__ __launch_bounds__(1024) void k_prep(const int* __restrict__ sp, int Esp,
                                               const int* __restrict__ tm, int Etm) {
    __shared__ int   cnt[2*NN];
    __shared__ float dv [2*NN];
    __shared__ int   sbuf[2048];
    int t = threadIdx.x;
    for (int i = t; i < 2*NN; i += 1024) cnt[i] = 0;
    __syncthreads();
    const int* spc = sp + Esp;
    const int* tmc = tm + Etm;
    for (int e = t; e < Esp; e += 1024) atomicAdd(&cnt[spc[e]], 1);
    for (int e = t; e < Etm; e += 1024) atomicAdd(&cnt[NN + tmc[e]], 1);
    __syncthreads();
    for (int i = t; i < 2*NN; i += 1024) {
        float d = rsqrtf((float)(cnt[i] + 1));
        dv[i] = d; g_dinv[i] = d;
    }
    for (int set = 0; set < 2; set++) {
        __syncthreads();
        for (int i = t; i < 2048; i += 1024) sbuf[i] = (i < NN) ? cnt[set*NN + i] : 0;
        __syncthreads();
        for (int off = 1; off < 2048; off <<= 1) {
            int v0 = (t >= off) ? sbuf[t - off] : 0;
            int i1 = t + 1024;
            int v1 = sbuf[i1 - off];
            __syncthreads();
            sbuf[t] += v0; sbuf[i1] += v1;
            __syncthreads();
        }
        int* ptr = g_ptr + set*(NN+1);
        for (int i = t; i <= NN; i += 1024) ptr[i] = (i == 0) ? 0 : sbuf[i-1];
    }
    __syncthreads();
    for (int i = t; i < 2*NN; i += 1024) cnt[i] = 0;
    __syncthreads();
    for (int e = t; e < Esp; e += 1024) {
        int r = sp[e], c = spc[e];
        float nrm = dv[r] * dv[c];
        int pos = g_ptr[c] + atomicAdd(&cnt[c], 1);
        g_esrc[pos] = r; g_enorm[pos] = nrm;
    }
    for (int e = t; e < Etm; e += 1024) {
        int r = tm[e], c = tmc[e];
        float nrm = dv[NN + r] * dv[NN + c];
        int pos = g_ptr[(NN+1) + c] + atomicAdd(&cnt[NN + c], 1);
        g_esrc[MAXE + pos] = r; g_enorm[MAXE + pos] = nrm;
    }
}

// ---------------- int8 2-digit quantization helpers ----------------
// quantize 8 fp32 values with scale s into hi/lo digit bytes
__device__ __forceinline__ void quant8(const float* v, float s, uint2& hi, uint2& lo) {
    uint32_t h[2] = {0,0}, l[2] = {0,0};
    #pragma unroll
    for (int e = 0; e < 8; e++) {
        float f  = v[e] * s;
        float ah = rintf(f);
        float al = rintf((f - ah) * 128.0f);
        uint32_t hb = ((uint32_t)(int)ah) & 0xff;
        uint32_t lb = ((uint32_t)(int)al) & 0xff;
        h[e>>2] |= hb << ((e & 3) * 8);
        l[e>>2] |= lb << ((e & 3) * 8);
    }
    hi.x = h[0]; hi.y = h[1];
    lo.x = l[0]; lo.y = l[1];
}
__device__ __forceinline__ float warp_max(float v) {
    #pragma unroll
    for (int o = 16; o > 0; o >>= 1)
        v = fmaxf(v, __shfl_xor_sync(0xffffffffu, v, o));
    return v;
}

// x fp32 [M,256] -> int8 digit images; 32 threads per row (8 ch each)
__global__ __launch_bounds__(256) void k_convA(const float* __restrict__ X) {
    int idx = blockIdx.x * 256 + threadIdx.x;
    int m = idx >> 5, lane = idx & 31;
    if (m >= MTOT) return;
    int k = lane * 8;
    float v[8];
    *(float4*)&v[0] = *(const float4*)&X[(size_t)m * CC + k];
    *(float4*)&v[4] = *(const float4*)&X[(size_t)m * CC + k + 4];
    float mx = 0.f;
    #pragma unroll
    for (int e = 0; e < 8; e++) mx = fmaxf(mx, fabsf(v[e]));
    mx = warp_max(mx);
    float s = (mx > 0.f) ? (127.0f / mx) : 0.f;
    if (lane == 0) g_qa[m] = mx * (1.0f/127.0f);
    uint2 hi, lo; quant8(v, s, hi, lo);
    int tile = m >> 7, mi = m & 127, chunk = k >> 6, kin = k & 63;
    size_t bo = (size_t)(tile*4 + chunk)*8192 + swz8(mi, kin);
    *(uint2*)(g_a8h + bo) = hi;
    *(uint2*)(g_a8l + bo) = lo;
}

// all three W fp32 [k=256][n=256] -> int8 digit images; 32 threads per column
__global__ __launch_bounds__(256) void k_convW3(const float* __restrict__ W1,
                                                const float* __restrict__ W2,
                                                const float* __restrict__ W3) {
    int gidx = blockIdx.x * 256 + threadIdx.x;    // 96 blocks: 3 layers x 256 cols x 32
    int layer = gidx >> 13;
    const float* W = (layer == 0) ? W1 : ((layer == 1) ? W2 : W3);
    int idx = gidx & 8191;
    int n = idx >> 5, lane = idx & 31;
    int k = lane * 8;
    float v[8];
    #pragma unroll
    for (int e = 0; e < 8; e++) v[e] = W[(size_t)(k+e)*CC + n];
    float mx = 0.f;
    #pragma unroll
    for (int e = 0; e < 8; e++) mx = fmaxf(mx, fabsf(v[e]));
    mx = warp_max(mx);
    float s = (mx > 0.f) ? (127.0f / mx) : 0.f;
    if (lane == 0) g_qb[layer*256 + n] = mx * (1.0f/127.0f);
    uint2 hi, lo; quant8(v, s, hi, lo);
    int nh = n >> 7, ni = n & 127, chunk = k >> 6, kin = k & 63;
    size_t bo = (size_t)layer*65536 + (size_t)(nh*4 + chunk)*8192 + swz8(ni, kin);
    *(uint2*)(g_b8h + bo) = hi;
    *(uint2*)(g_b8l + bo) = lo;
}

// ---------------- persistent IMMA GEMM: H = A @ W via int8 2-digit split ----------------
// grid (148): each CTA loops half-tiles (128x128). 512 thr = 16 warps (4m x 4n),
// warp tile 32x32. dyn smem: 4 stages x 32KB {Ah 8K | Al 8K | Bh 8K | Bl 8K}.
// acc1 = hi*hi; acc2 = hi*lo + lo*hi; out = (acc1 + acc2/128) * qa * qb.
#define GSTAGE 32768
#define GSM (4*GSTAGE)
__global__ __launch_bounds__(512) void k_gemm_mma(const char* __restrict__ Bh,
                                                  const char* __restrict__ Bl,
                                                  const float* __restrict__ qb,
                                                  float* __restrict__ H) {
    extern __shared__ __align__(128) char smc[];
    uint32_t sb = smem_u32(smc);
    int tid = threadIdx.x, wid = tid >> 5, lane = tid & 31;
    int bid = blockIdx.x;
    int mwarp = (wid >> 2) * 32, nwarp = (wid & 3) * 32;

    int nht = (NHT - bid + NSM - 1) / NSM;
    int total = nht * 4;

    int r15 = lane & 15, hi2 = lane >> 4;
    uint32_t aoff[2]; int asw[2];
    #pragma unroll
    for (int i = 0; i < 2; i++) {
        int mr = mwarp + i*16 + r15;
        aoff[i] = mr * 64; asw[i] = (mr >> 1) & 3;
    }
    uint32_t boff[2]; int bsw[2];
    #pragma unroll
    for (int jg = 0; jg < 2; jg++) {
        int nr = nwarp + jg*16 + r15;
        boff[jg] = nr * 64; bsw[jg] = (nr >> 1) & 3;
    }

    int acc1[2][4][4], acc2[2][4][4];
    #pragma unroll
    for (int i = 0; i < 2; i++)
        #pragma unroll
        for (int j = 0; j < 4; j++)
            #pragma unroll
            for (int q = 0; q < 4; q++) { acc1[i][j][q] = 0; acc2[i][j][q] = 0; }

    // issue chunk g: ht = bid + (g>>2)*148, chunk c = g&3, buffer g&3
    #define ISSUEG(g) do { \
        int _c = (g) & 3; \
        int _ht = bid + ((g) >> 2) * NSM; \
        int _tile = _ht >> 1, _nh = _ht & 1; \
        size_t _ab = (size_t)(_tile*4 + _c) * 8192; \
        size_t _bb = (size_t)(_nh*4 + _c) * 8192; \
        uint32_t so = sb + (uint32_t)((g) & 3) * GSTAGE; \
        uint32_t off = (uint32_t)tid * 16; \
        CPASYNC16(so +         off, g_a8h + _ab + off); \
        CPASYNC16(so +  8192 + off, g_a8l + _ab + off); \
        CPASYNC16(so + 16384 + off, Bh + _bb + off); \
        CPASYNC16(so + 24576 + off, Bl + _bb + off); \
        CPCOMMIT(); \
    } while (0)

    ISSUEG(0);
    if (total > 1) ISSUEG(1);
    if (total > 2) ISSUEG(2);
    for (int g = 0; g < total; g++) {
        int rem = total - g - 1;
        if (rem >= 2)      { CPWAIT(2); }
        else if (rem == 1) { CPWAIT(1); }
        else               { CPWAIT(0); }
        __syncthreads();
        uint32_t base = sb + (uint32_t)(g & 3) * GSTAGE;
        #pragma unroll
        for (int s = 0; s < 2; s++) {
            uint32_t ah[2][4], al[2][4];
            #pragma unroll
            for (int i = 0; i < 2; i++) {
                uint32_t kc = (uint32_t)((((s<<1)|hi2) ^ asw[i]) << 4);
                LDSM4(ah[i][0],ah[i][1],ah[i][2],ah[i][3], base + aoff[i] + kc);
                LDSM4(al[i][0],al[i][1],al[i][2],al[i][3], base + 8192 + aoff[i] + kc);
            }
            #pragma unroll
            for (int jg = 0; jg < 2; jg++) {
                uint32_t kc = (uint32_t)((((s<<1)|hi2) ^ bsw[jg]) << 4);
                uint32_t bh4[4], bl4[4];
                LDSM4(bh4[0],bh4[1],bh4[2],bh4[3], base + 16384 + boff[jg] + kc);
                LDSM4(bl4[0],bl4[1],bl4[2],bl4[3], base + 24576 + boff[jg] + kc);
                #pragma unroll
                for (int q = 0; q < 2; q++) {
                    int j = jg*2 + q;
                    #pragma unroll
                    for (int i = 0; i < 2; i++)
                        IMMA(acc1[i][j], ah[i], bh4[q], bh4[q+2]);
                    #pragma unroll
                    for (int i = 0; i < 2; i++)
                        IMMA(acc2[i][j], ah[i], bl4[q], bl4[q+2]);
                    #pragma unroll
                    for (int i = 0; i < 2; i++)
                        IMMA(acc2[i][j], al[i], bh4[q], bh4[q+2]);
                }
            }
        }
        if (g + 3 < total) ISSUEG(g+3);
        if ((g & 3) == 3) {
            // epilogue for finished half-tile
            int ht = bid + (g >> 2) * NSM;
            int tile = ht >> 1, nh = ht & 1;
            int rr = lane >> 2, cp = (lane & 3) * 2;
            #pragma unroll
            for (int i = 0; i < 2; i++) {
                size_t row = (size_t)tile*128 + mwarp + i*16 + rr;
                float qa0 = g_qa[row], qa1 = g_qa[row + 8];
                #pragma unroll
                for (int j = 0; j < 4; j++) {
                    int col = nh*128 + nwarp + j*8 + cp;
                    float qb0 = qb[col], qb1 = qb[col+1];
                    float v0 = ((float)acc1[i][j][0] + (float)acc2[i][j][0]*0.0078125f)*qa0*qb0;
                    float v1 = ((float)acc1[i][j][1] + (float)acc2[i][j][1]*0.0078125f)*qa0*qb1;
                    float v2 = ((float)acc1[i][j][2] + (float)acc2[i][j][2]*0.0078125f)*qa1*qb0;
                    float v3 = ((float)acc1[i][j][3] + (float)acc2[i][j][3]*0.0078125f)*qa1*qb1;
                    *(float2*)&H[row*CC + col]     = make_float2(v0, v1);
                    *(float2*)&H[(row+8)*CC + col] = make_float2(v2, v3);
                }
            }
            #pragma unroll
            for (int i = 0; i < 2; i++)
                #pragma unroll
                for (int j = 0; j < 4; j++)
                    #pragma unroll
                    for (int q = 0; q < 4; q++) { acc1[i][j][q] = 0; acc2[i][j][q] = 0; }
        }
    }
}

// ---------------- aggregation ----------------
// acc = sum_in-edges norm*h[b,src,:] + dinv^2*h[b,n,:] + bias (+res), relu.
// 32-thread groups (1 row each, 8 ch/thread), 8 batches per block (shared metadata).
// write_img -> int8 digit images + qa row scales.
__global__ __launch_bounds__(256) void k_agg(const float* __restrict__ h, int set,
                                             const float* __restrict__ bias,
                                             const float* __restrict__ residual,
                                             float* __restrict__ out, int write_img) {
    int g    = threadIdx.x >> 5;           // batch sub-group 0..7
    int lane = threadIdx.x & 31;           // channel/8
    int n = blockIdx.x;
    int b = blockIdx.y * 8 + g;
    int ch = lane * 8;

    const int* ptr = g_ptr + set*(NN+1);
    int p0 = __ldg(&ptr[n]), p1 = __ldg(&ptr[n+1]);
    float dn = __ldg(&g_dinv[set*NN + n]);
    size_t bbase = (size_t)b * NN;
    size_t base  = (bbase + n) * CC + ch;

    float4 a0 = *(const float4*)&h[base];
    float4 a1 = *(const float4*)&h[base + 4];
    float w = dn * dn;
    a0.x *= w; a0.y *= w; a0.z *= w; a0.w *= w;
    a1.x *= w; a1.y *= w; a1.z *= w; a1.w *= w;

    int off = set*MAXE;
    int j = p0;
    for (; j + 2 <= p1; j += 2) {
        int   s0 = __ldg(&g_esrc [off + j]);
        int   s1 = __ldg(&g_esrc [off + j + 1]);
        float w0 = __ldg(&g_enorm[off + j]);
        float w1 = __ldg(&g_enorm[off + j + 1]);
        size_t r0 = (bbase + s0)*CC + ch;
        size_t r1 = (bbase + s1)*CC + ch;
        float4 u0 = *(const float4*)&h[r0];
        float4 u1 = *(const float4*)&h[r0 + 4];
        float4 v0 = *(const float4*)&h[r1];
        float4 v1 = *(const float4*)&h[r1 + 4];
        a0.x += w0*u0.x + w1*v0.x; a0.y += w0*u0.y + w1*v0.y;
        a0.z += w0*u0.z + w1*v0.z; a0.w += w0*u0.w + w1*v0.w;
        a1.x += w0*u1.x + w1*v1.x; a1.y += w0*u1.y + w1*v1.y;
        a1.z += w0*u1.z + w1*v1.z; a1.w += w0*u1.w + w1*v1.w;
    }
    if (j < p1) {
        int   s0 = __ldg(&g_esrc [off + j]);
        float w0 = __ldg(&g_enorm[off + j]);
        size_t r0 = (bbase + s0)*CC + ch;
        float4 u0 = *(const float4*)&h[r0];
        float4 u1 = *(const float4*)&h[r0 + 4];
        a0.x += w0*u0.x; a0.y += w0*u0.y; a0.z += w0*u0.z; a0.w += w0*u0.w;
        a1.x += w0*u1.x; a1.y += w0*u1.y; a1.z += w0*u1.z; a1.w += w0*u1.w;
    }

    float4 bi0 = *(const float4*)&bias[ch];
    float4 bi1 = *(const float4*)&bias[ch + 4];
    a0.x += bi0.x; a0.y += bi0.y; a0.z += bi0.z; a0.w += bi0.w;
    a1.x += bi1.x; a1.y += bi1.y; a1.z += bi1.z; a1.w += bi1.w;
    if (residual) {
        float4 r0 = *(const float4*)&residual[base];
        float4 r1 = *(const float4*)&residual[base + 4];
        a0.x += r0.x; a0.y += r0.y; a0.z += r0.z; a0.w += r0.w;
        a1.x += r1.x; a1.y += r1.y; a1.z += r1.z; a1.w += r1.w;
    }
    float v[8];
    v[0]=fmaxf(a0.x,0.f); v[1]=fmaxf(a0.y,0.f); v[2]=fmaxf(a0.z,0.f); v[3]=fmaxf(a0.w,0.f);
    v[4]=fmaxf(a1.x,0.f); v[5]=fmaxf(a1.y,0.f); v[6]=fmaxf(a1.z,0.f); v[7]=fmaxf(a1.w,0.f);

    if (write_img) {
        float mx = 0.f;
        #pragma unroll
        for (int e = 0; e < 8; e++) mx = fmaxf(mx, v[e]);   // v >= 0 after relu
        mx = warp_max(mx);
        float s = (mx > 0.f) ? (127.0f / mx) : 0.f;
        int m = (int)(bbase + n);
        if (lane == 0) g_qa[m] = mx * (1.0f/127.0f);
        uint2 hi, lo; quant8(v, s, hi, lo);
        int tile = m >> 7, mi = m & 127, chunk = ch >> 6, kin = ch & 63;
        size_t bo = (size_t)(tile*4 + chunk)*8192 + swz8(mi, kin);
        *(uint2*)(g_a8h + bo) = hi;
        *(uint2*)(g_a8l + bo) = lo;
    } else {
        *(float4*)&out[base]     = make_float4(v[0], v[1], v[2], v[3]);
        *(float4*)&out[base + 4] = make_float4(v[4], v[5], v[6], v[7]);
    }
}

// ---------------- launch ----------------
extern "C" void kernel_launch(void* const* d_in, const int* in_sizes, int n_in,
                              void* d_out, int out_size) {
    const float* x  = (const float*)d_in[0];
    const float* W1 = (const float*)d_in[1];
    const float* b1 = (const float*)d_in[2];
    const float* W2 = (const float*)d_in[3];
    const float* b2 = (const float*)d_in[4];
    const float* W3 = (const float*)d_in[5];
    const float* b3 = (const float*)d_in[6];
    const int*   sp = (const int*)d_in[7];
    const int*   tm = (const int*)d_in[8];
    int Esp = in_sizes[7] / 2;
    int Etm = in_sizes[8] / 2;
    float* out = (float*)d_out;

    float *h, *qb; char *bh, *bl;
    cudaGetSymbolAddress((void**)&h,  g_h);
    cudaGetSymbolAddress((void**)&bh, g_b8h);
    cudaGetSymbolAddress((void**)&bl, g_b8l);
    cudaGetSymbolAddress((void**)&qb, g_qb);

    cudaFuncSetAttribute(k_gemm_mma, cudaFuncAttributeMaxDynamicSharedMemorySize, GSM);

    dim3 ga(NN, BB/8);                // (1700, 8)

    k_convA <<<(MTOT*32 + 255)/256, 256>>>(x);
    k_convW3<<<96, 256>>>(W1, W2, W3);
    k_prep  <<<1, 1024>>>(sp, Esp, tm, Etm);

    // conv1 (4th launch — profiled by ncu)
    k_gemm_mma<<<NSM, 512, GSM>>>(bh, bl, qb, h);
    k_agg<<<ga, 256>>>(h, 0, b1, nullptr, nullptr, 1);
    // conv2
    k_gemm_mma<<<NSM, 512, GSM>>>(bh + 65536, bl + 65536, qb + 256, h);
    k_agg<<<ga, 256>>>(h, 1, b2, nullptr, nullptr, 1);
    // conv3
    k_gemm_mma<<<NSM, 512, GSM>>>(bh + 2*65536, bl + 2*65536, qb + 512, h);
    k_agg<<<ga, 256>>>(h, 0, b3, x, out, 0);
}

// round 10
// speedup vs baseline: 2.2709x; 2.2709x over previous
#include <cuda_runtime.h>
#include <cuda_fp16.h>
#include <cstdint>

typedef unsigned long long ull;

#define BB 64
#define NN 1700
#define CC 256
#define MAXE 16384
#define MTOT (BB*NN)
#define MTILES (MTOT/128)          // 850
#define NSM 148

// ---------------- scratch (device globals; no allocation allowed) ----------------
__device__ float g_h[(size_t)BB*NN*CC];            // GEMM output (fp32)
__device__ __half g_ah[(size_t)MTOT*CC];           // A hi image (fp16, chunked+swizzled)
__device__ __half g_al[(size_t)MTOT*CC];           // A lo image (fp16 residual)
__device__ __half g_bh[3*65536];                   // B single-fp16 images per layer
__device__ int   g_ptr[2*(NN+1)];
__device__ float g_dinv[2*NN];
__device__ int   g_esrc[2*MAXE];
__device__ float g_enorm[2*MAXE];

// ---------------- PTX helpers (all sm_80-class: valid for compute_103) ----------------
__device__ __forceinline__ uint32_t smem_u32(const void* p) {
    uint32_t a;
    asm("{ .reg .u64 t; cvta.to.shared.u64 t, %1; cvt.u32.u64 %0, t; }" : "=r"(a) : "l"(p));
    return a;
}
#define LDSM4(r0,r1,r2,r3,addr) \
    asm volatile("ldmatrix.sync.aligned.m8n8.x4.shared.b16 {%0,%1,%2,%3}, [%4];" \
        : "=r"(r0),"=r"(r1),"=r"(r2),"=r"(r3) : "r"(addr))
#define MMA16816(d, a, b0, b1) \
    asm volatile("mma.sync.aligned.m16n8k16.row.col.f32.f16.f16.f32 " \
        "{%0,%1,%2,%3},{%4,%5,%6,%7},{%8,%9},{%0,%1,%2,%3};" \
        : "+f"((d)[0]),"+f"((d)[1]),"+f"((d)[2]),"+f"((d)[3]) \
        : "r"((a)[0]),"r"((a)[1]),"r"((a)[2]),"r"((a)[3]), "r"(b0),"r"(b1))
#define CPASYNC16(dst, src) \
    asm volatile("cp.async.cg.shared.global [%0], [%1], 16;" :: "r"(dst), "l"(src))
#define CPCOMMIT() asm volatile("cp.async.commit_group;")
#define CPWAIT(n)  asm volatile("cp.async.wait_group %0;" :: "n"(n))

// chunked image element offset within a 128x32 block (64B rows), 16B-chunk XOR swizzle
__device__ __forceinline__ uint32_t swz_elem(int r, int kin) {
    return (uint32_t)(r*32 + ((((kin>>3) ^ ((r>>1)&3)))<<3) + (kin&7));
}

// ---------------- fused prep: histogram -> scan -> dinv -> CSR fill, both edge sets ----------------
__global__ __launch_bounds__(1024) void k_prep(const int* __restrict__ sp, int Esp,
                                               const int* __restrict__ tm, int Etm) {
    __shared__ int   cnt[2*NN];
    __shared__ float dv [2*NN];
    __shared__ int   sbuf[2048];
    int t = threadIdx.x;
    for (int i = t; i < 2*NN; i += 1024) cnt[i] = 0;
    __syncthreads();
    const int* spc = sp + Esp;
    const int* tmc = tm + Etm;
    for (int e = t; e < Esp; e += 1024) atomicAdd(&cnt[spc[e]], 1);
    for (int e = t; e < Etm; e += 1024) atomicAdd(&cnt[NN + tmc[e]], 1);
    __syncthreads();
    for (int i = t; i < 2*NN; i += 1024) {
        float d = rsqrtf((float)(cnt[i] + 1));
        dv[i] = d; g_dinv[i] = d;
    }
    for (int set = 0; set < 2; set++) {
        __syncthreads();
        for (int i = t; i < 2048; i += 1024) sbuf[i] = (i < NN) ? cnt[set*NN + i] : 0;
        __syncthreads();
        for (int off = 1; off < 2048; off <<= 1) {
            int v0 = (t >= off) ? sbuf[t - off] : 0;
            int i1 = t + 1024;
            int v1 = sbuf[i1 - off];
            __syncthreads();
            sbuf[t] += v0; sbuf[i1] += v1;
            __syncthreads();
        }
        int* ptr = g_ptr + set*(NN+1);
        for (int i = t; i <= NN; i += 1024) ptr[i] = (i == 0) ? 0 : sbuf[i-1];
    }
    __syncthreads();
    for (int i = t; i < 2*NN; i += 1024) cnt[i] = 0;
    __syncthreads();
    for (int e = t; e < Esp; e += 1024) {
        int r = sp[e], c = spc[e];
        float nrm = dv[r] * dv[c];
        int pos = g_ptr[c] + atomicAdd(&cnt[c], 1);
        g_esrc[pos] = r; g_enorm[pos] = nrm;
    }
    for (int e = t; e < Etm; e += 1024) {
        int r = tm[e], c = tmc[e];
        float nrm = dv[NN + r] * dv[NN + c];
        int pos = g_ptr[(NN+1) + c] + atomicAdd(&cnt[NN + c], 1);
        g_esrc[MAXE + pos] = r; g_enorm[MAXE + pos] = nrm;
    }
}

// ---------------- fp16 hi/lo split ----------------
__device__ __forceinline__ void split4h(float4 v, uint2& hi, uint2& lo) {
    __half h0 = __float2half(v.x), h1 = __float2half(v.y),
           h2 = __float2half(v.z), h3 = __float2half(v.w);
    __half l0 = __float2half(v.x - __half2float(h0));
    __half l1 = __float2half(v.y - __half2float(h1));
    __half l2 = __float2half(v.z - __half2float(h2));
    __half l3 = __float2half(v.w - __half2float(h3));
    __half2 hA = __halves2half2(h0, h1), hB = __halves2half2(h2, h3);
    __half2 lA = __halves2half2(l0, l1), lB = __halves2half2(l2, l3);
    hi.x = *(uint32_t*)&hA; hi.y = *(uint32_t*)&hB;
    lo.x = *(uint32_t*)&lA; lo.y = *(uint32_t*)&lB;
}

// x fp32 [M,256] -> fp16 hi/lo images: [tile][chunk(8)][128x32 swizzled]
__global__ __launch_bounds__(256) void k_convA(const float* __restrict__ X) {
    int idx = blockIdx.x * 256 + threadIdx.x;
    int m = idx >> 6, lane = idx & 63;
    if (m >= MTOT) return;
    int k = lane * 4;
    float4 v = *(const float4*)&X[(size_t)m * CC + k];
    uint2 hi, lo; split4h(v, hi, lo);
    int tile = m >> 7, mi = m & 127, chunk = k >> 5, kin = k & 31;
    size_t eo = (size_t)(tile*8 + chunk)*4096 + swz_elem(mi, kin);
    *(uint2*)(g_ah + eo) = hi;
    *(uint2*)(g_al + eo) = lo;
}

// all three W fp32 [k=256][n=256] -> single fp16 images (layer = blockIdx.x/64)
__global__ __launch_bounds__(256) void k_convW3(const float* __restrict__ W1,
                                                const float* __restrict__ W2,
                                                const float* __restrict__ W3) {
    int layer = blockIdx.x >> 6;
    const float* W = (layer == 0) ? W1 : ((layer == 1) ? W2 : W3);
    int idx = (blockIdx.x & 63) * 256 + threadIdx.x;
    int n = idx >> 6, kq = idx & 63;
    if (n >= 256) return;
    int k = kq * 4;
    __half w0 = __float2half(W[(size_t)(k+0)*CC + n]);
    __half w1 = __float2half(W[(size_t)(k+1)*CC + n]);
    __half w2 = __float2half(W[(size_t)(k+2)*CC + n]);
    __half w3 = __float2half(W[(size_t)(k+3)*CC + n]);
    __half2 pA = __halves2half2(w0, w1), pB = __halves2half2(w2, w3);
    uint2 pk; pk.x = *(uint32_t*)&pA; pk.y = *(uint32_t*)&pB;
    int nh = n >> 7, ni = n & 127, chunk = k >> 5, kin = k & 31;
    size_t eo = (size_t)layer*65536 + (size_t)(nh*8 + chunk)*4096 + swz_elem(ni, kin);
    *(uint2*)(g_bh + eo) = pk;
}

// ---------------- persistent HMMA GEMM: H = A @ W via fp16 2-product split ----------------
// grid (148): each CTA loops tiles bid, bid+148, ... CTA tile 128x256, 512 thr =
// 16 warps (4m x 4n), warp tile 32x64. dyn smem: 4 stages x 32KB {Ahi 8K | Alo 8K | B 16K}.
// D = ah*b + al*b  (B single fp16; error = B quantization ~2^-11)
#define GSTAGE 32768
#define GSM (4*GSTAGE)
__global__ __launch_bounds__(512) void k_gemm_mma(const __half* __restrict__ Bimg,
                                                  float* __restrict__ H) {
    extern __shared__ __align__(128) char smc[];
    uint32_t sb = smem_u32(smc);
    int tid = threadIdx.x, wid = tid >> 5, lane = tid & 31;
    int bid = blockIdx.x;
    int mwarp = (wid >> 2) * 32, nwarp = (wid & 3) * 64;

    int nt = (MTILES - bid + NSM - 1) / NSM;   // tiles for this CTA
    int total = nt * 8;                        // chunk count (k32 chunks)

    const char* gB = (const char*)Bimg;

    // ldmatrix address precompute
    int r15 = lane & 15, hi2 = lane >> 4;
    uint32_t aoff[2]; int asw[2];
    #pragma unroll
    for (int i = 0; i < 2; i++) {
        int mr = mwarp + i*16 + r15;
        aoff[i] = mr * 64; asw[i] = (mr >> 1) & 3;
    }
    uint32_t boff[4]; int bsw[4];
    uint32_t nhbase = (uint32_t)(nwarp >> 7) * 8192;
    #pragma unroll
    for (int j = 0; j < 4; j++) {
        int nr = (nwarp & 127) + j*16 + r15;
        boff[j] = nhbase + nr * 64; bsw[j] = (nr >> 1) & 3;
    }

    float d[2][8][4];
    #pragma unroll
    for (int i = 0; i < 2; i++)
        #pragma unroll
        for (int j = 0; j < 8; j++)
            #pragma unroll
            for (int q = 0; q < 4; q++) d[i][j][q] = 0.f;

    // issue chunk g: tile = bid + (g>>3)*148, chunk c = g&7, buffer g&3
    // per thread 16B x4: A hi 8K, A lo 8K, B nh0 8K, B nh1 8K
    #define ISSUEG(g) do { \
        int _c = (g) & 7; \
        size_t _tb = (size_t)(bid + ((g) >> 3) * NSM) * 65536 + (size_t)_c * 8192; \
        uint32_t so = sb + (uint32_t)((g) & 3) * GSTAGE; \
        uint32_t off = (uint32_t)tid * 16; \
        CPASYNC16(so +         off, (const char*)g_ah + _tb + off); \
        CPASYNC16(so +  8192 + off, (const char*)g_al + _tb + off); \
        _Pragma("unroll") \
        for (int nh_ = 0; nh_ < 2; nh_++) { \
            size_t gb = (size_t)(nh_*8 + _c) * 8192; \
            CPASYNC16(so + 16384 + nh_*8192 + off, gB + gb + off); \
        } \
        CPCOMMIT(); \
    } while (0)

    ISSUEG(0);
    if (total > 1) ISSUEG(1);
    if (total > 2) ISSUEG(2);
    for (int g = 0; g < total; g++) {
        int rem = total - g - 1;
        if (rem >= 2)      { CPWAIT(2); }
        else if (rem == 1) { CPWAIT(1); }
        else               { CPWAIT(0); }
        __syncthreads();                       // single barrier per chunk
        uint32_t base = sb + (uint32_t)(g & 3) * GSTAGE;
        #pragma unroll
        for (int s = 0; s < 2; s++) {
            uint32_t ah[2][4], al[2][4];
            #pragma unroll
            for (int i = 0; i < 2; i++) {
                uint32_t kc = (uint32_t)((((s<<1)|hi2) ^ asw[i]) << 4);
                LDSM4(ah[i][0],ah[i][1],ah[i][2],ah[i][3], base + aoff[i] + kc);
                LDSM4(al[i][0],al[i][1],al[i][2],al[i][3], base + 8192 + aoff[i] + kc);
            }
            #pragma unroll
            for (int jp = 0; jp < 2; jp++) {   // j pair {2jp, 2jp+1}
                uint32_t bf[2][4];
                #pragma unroll
                for (int q = 0; q < 2; q++) {
                    int j = jp*2 + q;
                    uint32_t kc = (uint32_t)((((s<<1)|hi2) ^ bsw[j]) << 4);
                    LDSM4(bf[q][0],bf[q][1],bf[q][2],bf[q][3], base + 16384 + boff[j] + kc);
                }
                // ah*b: 8 MMAs into 8 distinct accumulators
                #pragma unroll
                for (int q = 0; q < 2; q++)
                    #pragma unroll
                    for (int i = 0; i < 2; i++) {
                        MMA16816(d[i][4*jp+2*q],   ah[i], bf[q][0], bf[q][2]);
                        MMA16816(d[i][4*jp+2*q+1], ah[i], bf[q][1], bf[q][3]);
                    }
                // al*b: same 8 accumulators, reuse distance 8
                #pragma unroll
                for (int q = 0; q < 2; q++)
                    #pragma unroll
                    for (int i = 0; i < 2; i++) {
                        MMA16816(d[i][4*jp+2*q],   al[i], bf[q][0], bf[q][2]);
                        MMA16816(d[i][4*jp+2*q+1], al[i], bf[q][1], bf[q][3]);
                    }
            }
        }
        if (g + 3 < total) ISSUEG(g+3);        // writes buf (g-1)&3: safe past this barrier
        if ((g & 7) == 7) {
            // epilogue for finished tile (overlaps in-flight cp.async of next tile)
            int tile = bid + (g >> 3) * NSM;
            int rr = lane >> 2, cp = (lane & 3) * 2;
            #pragma unroll
            for (int i = 0; i < 2; i++) {
                size_t row = (size_t)tile*128 + mwarp + i*16 + rr;
                #pragma unroll
                for (int j = 0; j < 8; j++) {
                    int col = nwarp + j*8 + cp;
                    *(float2*)&H[row*CC + col]     = make_float2(d[i][j][0], d[i][j][1]);
                    *(float2*)&H[(row+8)*CC + col] = make_float2(d[i][j][2], d[i][j][3]);
                }
            }
            #pragma unroll
            for (int i = 0; i < 2; i++)
                #pragma unroll
                for (int j = 0; j < 8; j++)
                    #pragma unroll
                    for (int q = 0; q < 4; q++) d[i][j][q] = 0.f;
        }
    }
}

// ---------------- aggregation ----------------
// acc = sum_in-edges norm*h[b,src,:] + dinv^2*h[b,n,:] + bias (+res), relu.
// block = 1 node x 4 batches (metadata shared); write_img -> fp16 hi/lo A images.
__global__ __launch_bounds__(256) void k_agg(const float* __restrict__ h, int set,
                                             const float* __restrict__ bias,
                                             const float* __restrict__ residual,
                                             float* __restrict__ out, int write_img) {
    int g    = threadIdx.x >> 6;           // batch sub-group 0..3
    int lane = threadIdx.x & 63;           // channel/4
    int n = blockIdx.x;
    int b = blockIdx.y * 4 + g;

    const int* ptr = g_ptr + set*(NN+1);
    int p0 = __ldg(&ptr[n]), p1 = __ldg(&ptr[n+1]);
    float dn = __ldg(&g_dinv[set*NN + n]);
    size_t bbase = (size_t)b * NN;
    size_t base  = (bbase + n) * CC + lane*4;

    float4 sv = *(const float4*)&h[base];
    float w = dn * dn;
    float4 acc;
    acc.x = w*sv.x; acc.y = w*sv.y; acc.z = w*sv.z; acc.w = w*sv.w;

    int off = set*MAXE;
    int j = p0;
    for (; j + 4 <= p1; j += 4) {
        int   s0 = __ldg(&g_esrc [off + j]);
        int   s1 = __ldg(&g_esrc [off + j + 1]);
        int   s2 = __ldg(&g_esrc [off + j + 2]);
        int   s3 = __ldg(&g_esrc [off + j + 3]);
        float w0 = __ldg(&g_enorm[off + j]);
        float w1 = __ldg(&g_enorm[off + j + 1]);
        float w2 = __ldg(&g_enorm[off + j + 2]);
        float w3 = __ldg(&g_enorm[off + j + 3]);
        float4 v0 = *(const float4*)&h[(bbase + s0)*CC + lane*4];
        float4 v1 = *(const float4*)&h[(bbase + s1)*CC + lane*4];
        float4 v2 = *(const float4*)&h[(bbase + s2)*CC + lane*4];
        float4 v3 = *(const float4*)&h[(bbase + s3)*CC + lane*4];
        acc.x += w0*v0.x + w1*v1.x + w2*v2.x + w3*v3.x;
        acc.y += w0*v0.y + w1*v1.y + w2*v2.y + w3*v3.y;
        acc.z += w0*v0.z + w1*v1.z + w2*v2.z + w3*v3.z;
        acc.w += w0*v0.w + w1*v1.w + w2*v2.w + w3*v3.w;
    }
    for (; j < p1; ++j) {
        int   s0 = __ldg(&g_esrc [off + j]);
        float w0 = __ldg(&g_enorm[off + j]);
        float4 v0 = *(const float4*)&h[(bbase + s0)*CC + lane*4];
        acc.x += w0*v0.x; acc.y += w0*v0.y; acc.z += w0*v0.z; acc.w += w0*v0.w;
    }

    float4 bi = *(const float4*)&bias[lane*4];
    acc.x += bi.x; acc.y += bi.y; acc.z += bi.z; acc.w += bi.w;
    if (residual) {
        float4 rv = *(const float4*)&residual[base];
        acc.x += rv.x; acc.y += rv.y; acc.z += rv.z; acc.w += rv.w;
    }
    acc.x = fmaxf(acc.x, 0.f); acc.y = fmaxf(acc.y, 0.f);
    acc.z = fmaxf(acc.z, 0.f); acc.w = fmaxf(acc.w, 0.f);

    if (write_img) {
        uint2 hi, lo; split4h(acc, hi, lo);
        int m = (int)(bbase + n);
        int tile = m >> 7, mi = m & 127, k = lane*4, chunk = k >> 5, kin = k & 31;
        size_t eo = (size_t)(tile*8 + chunk)*4096 + swz_elem(mi, kin);
        *(uint2*)(g_ah + eo) = hi;
        *(uint2*)(g_al + eo) = lo;
    } else {
        *(float4*)&out[base] = acc;
    }
}

// ---------------- launch ----------------
extern "C" void kernel_launch(void* const* d_in, const int* in_sizes, int n_in,
                              void* d_out, int out_size) {
    const float* x  = (const float*)d_in[0];
    const float* W1 = (const float*)d_in[1];
    const float* b1 = (const float*)d_in[2];
    const float* W2 = (const float*)d_in[3];
    const float* b2 = (const float*)d_in[4];
    const float* W3 = (const float*)d_in[5];
    const float* b3 = (const float*)d_in[6];
    const int*   sp = (const int*)d_in[7];
    const int*   tm = (const int*)d_in[8];
    int Esp = in_sizes[7] / 2;
    int Etm = in_sizes[8] / 2;
    float* out = (float*)d_out;

    float* h; __half* bh;
    cudaGetSymbolAddress((void**)&h,  g_h);
    cudaGetSymbolAddress((void**)&bh, g_bh);

    cudaFuncSetAttribute(k_gemm_mma, cudaFuncAttributeMaxDynamicSharedMemorySize, GSM);

    dim3 ga(NN, BB/4);                // (1700, 16)

    k_convA <<<(MTOT*64 + 255)/256, 256>>>(x);
    k_convW3<<<192, 256>>>(W1, W2, W3);
    k_prep  <<<1, 1024>>>(sp, Esp, tm, Etm);

    // conv1 (4th launch — profiled by ncu)
    k_gemm_mma<<<NSM, 512, GSM>>>(bh, h);
    k_agg<<<ga, 256>>>(h, 0, b1, nullptr, nullptr, 1);
    // conv2
    k_gemm_mma<<<NSM, 512, GSM>>>(bh + 65536, h);
    k_agg<<<ga, 256>>>(h, 1, b2, nullptr, nullptr, 1);
    // conv3
    k_gemm_mma<<<NSM, 512, GSM>>>(bh + 2*65536, h);
    k_agg<<<ga, 256>>>(h, 0, b3, x, out, 0);
}

// round 11
// speedup vs baseline: 3.1108x; 1.3699x over previous
#include <cuda_runtime.h>
#include <cuda_fp16.h>
#include <cstdint>

typedef unsigned long long ull;

#define BB 64
#define NN 1700
#define CC 256
#define MAXE 16384
#define MTOT (BB*NN)
#define MTILES (MTOT/128)          // 850
#define NSM 148

// ---------------- scratch (device globals; no allocation allowed) ----------------
__device__ __half g_ax[(size_t)MTOT*CC];           // A input images (fp16, chunked+swizzled)
__device__ __half g_hx[(size_t)MTOT*CC];           // H output images (fp16, same layout)
__device__ __half g_bh[3*65536];                   // B fp16 images per layer
__device__ int   g_ptr[2*(NN+1)];
__device__ float g_dinv[2*NN];
__device__ int   g_esrc[2*MAXE];
__device__ float g_enorm[2*MAXE];

// ---------------- PTX helpers (all sm_80-class: valid for compute_103) ----------------
__device__ __forceinline__ uint32_t smem_u32(const void* p) {
    uint32_t a;
    asm("{ .reg .u64 t; cvta.to.shared.u64 t, %1; cvt.u32.u64 %0, t; }" : "=r"(a) : "l"(p));
    return a;
}
#define LDSM4(r0,r1,r2,r3,addr) \
    asm volatile("ldmatrix.sync.aligned.m8n8.x4.shared.b16 {%0,%1,%2,%3}, [%4];" \
        : "=r"(r0),"=r"(r1),"=r"(r2),"=r"(r3) : "r"(addr))
#define MMA16816(d, a, b0, b1) \
    asm volatile("mma.sync.aligned.m16n8k16.row.col.f32.f16.f16.f32 " \
        "{%0,%1,%2,%3},{%4,%5,%6,%7},{%8,%9},{%0,%1,%2,%3};" \
        : "+f"((d)[0]),"+f"((d)[1]),"+f"((d)[2]),"+f"((d)[3]) \
        : "r"((a)[0]),"r"((a)[1]),"r"((a)[2]),"r"((a)[3]), "r"(b0),"r"(b1))
#define CPASYNC16(dst, src) \
    asm volatile("cp.async.cg.shared.global [%0], [%1], 16;" :: "r"(dst), "l"(src))
#define CPCOMMIT() asm volatile("cp.async.commit_group;")
#define CPWAIT(n)  asm volatile("cp.async.wait_group %0;" :: "n"(n))

// chunked image element offset within a 128x32 block (64B rows), 16B-chunk XOR swizzle
__device__ __forceinline__ uint32_t swz_elem(int r, int kin) {
    return (uint32_t)(r*32 + ((((kin>>3) ^ ((r>>1)&3)))<<3) + (kin&7));
}
// full image element offset for row m (0..MTOT), channel ch (0..255)
__device__ __forceinline__ size_t img_off(int m, int ch) {
    int tile = m >> 7, mi = m & 127, chunk = ch >> 5, kin = ch & 31;
    return (size_t)(tile*8 + chunk)*4096 + swz_elem(mi, kin);
}

// ---------------- fused prep: histogram -> scan -> dinv -> CSR fill, both edge sets ----------------
__global__ __launch_bounds__(1024) void k_prep(const int* __restrict__ sp, int Esp,
                                               const int* __restrict__ tm, int Etm) {
    __shared__ int   cnt[2*NN];
    __shared__ float dv [2*NN];
    __shared__ int   sbuf[2048];
    int t = threadIdx.x;
    for (int i = t; i < 2*NN; i += 1024) cnt[i] = 0;
    __syncthreads();
    const int* spc = sp + Esp;
    const int* tmc = tm + Etm;
    for (int e = t; e < Esp; e += 1024) atomicAdd(&cnt[spc[e]], 1);
    for (int e = t; e < Etm; e += 1024) atomicAdd(&cnt[NN + tmc[e]], 1);
    __syncthreads();
    for (int i = t; i < 2*NN; i += 1024) {
        float d = rsqrtf((float)(cnt[i] + 1));
        dv[i] = d; g_dinv[i] = d;
    }
    for (int set = 0; set < 2; set++) {
        __syncthreads();
        for (int i = t; i < 2048; i += 1024) sbuf[i] = (i < NN) ? cnt[set*NN + i] : 0;
        __syncthreads();
        for (int off = 1; off < 2048; off <<= 1) {
            int v0 = (t >= off) ? sbuf[t - off] : 0;
            int i1 = t + 1024;
            int v1 = sbuf[i1 - off];
            __syncthreads();
            sbuf[t] += v0; sbuf[i1] += v1;
            __syncthreads();
        }
        int* ptr = g_ptr + set*(NN+1);
        for (int i = t; i <= NN; i += 1024) ptr[i] = (i == 0) ? 0 : sbuf[i-1];
    }
    __syncthreads();
    for (int i = t; i < 2*NN; i += 1024) cnt[i] = 0;
    __syncthreads();
    for (int e = t; e < Esp; e += 1024) {
        int r = sp[e], c = spc[e];
        float nrm = dv[r] * dv[c];
        int pos = g_ptr[c] + atomicAdd(&cnt[c], 1);
        g_esrc[pos] = r; g_enorm[pos] = nrm;
    }
    for (int e = t; e < Etm; e += 1024) {
        int r = tm[e], c = tmc[e];
        float nrm = dv[NN + r] * dv[NN + c];
        int pos = g_ptr[(NN+1) + c] + atomicAdd(&cnt[NN + c], 1);
        g_esrc[MAXE + pos] = r; g_enorm[MAXE + pos] = nrm;
    }
}

// ---------------- pack/unpack helpers ----------------
__device__ __forceinline__ uint4 pack8h(const float* v) {
    __half2 p0 = __floats2half2_rn(v[0], v[1]);
    __half2 p1 = __floats2half2_rn(v[2], v[3]);
    __half2 p2 = __floats2half2_rn(v[4], v[5]);
    __half2 p3 = __floats2half2_rn(v[6], v[7]);
    uint4 r;
    r.x = *(uint32_t*)&p0; r.y = *(uint32_t*)&p1;
    r.z = *(uint32_t*)&p2; r.w = *(uint32_t*)&p3;
    return r;
}
__device__ __forceinline__ void unpack8h(uint4 p, float* v) {
    float2 f0 = __half22float2(*(__half2*)&p.x);
    float2 f1 = __half22float2(*(__half2*)&p.y);
    float2 f2 = __half22float2(*(__half2*)&p.z);
    float2 f3 = __half22float2(*(__half2*)&p.w);
    v[0]=f0.x; v[1]=f0.y; v[2]=f1.x; v[3]=f1.y;
    v[4]=f2.x; v[5]=f2.y; v[6]=f3.x; v[7]=f3.y;
}

// x fp32 [M,256] -> fp16 A image; 32 threads per row (8 ch each)
__global__ __launch_bounds__(256) void k_convA(const float* __restrict__ X) {
    int idx = blockIdx.x * 256 + threadIdx.x;
    int m = idx >> 5, lane = idx & 31;
    if (m >= MTOT) return;
    int ch = lane * 8;
    float v[8];
    *(float4*)&v[0] = *(const float4*)&X[(size_t)m * CC + ch];
    *(float4*)&v[4] = *(const float4*)&X[(size_t)m * CC + ch + 4];
    *(uint4*)(g_ax + img_off(m, ch)) = pack8h(v);
}

// all three W fp32 [k=256][n=256] -> single fp16 images (layer = blockIdx.x/64)
__global__ __launch_bounds__(256) void k_convW3(const float* __restrict__ W1,
                                                const float* __restrict__ W2,
                                                const float* __restrict__ W3) {
    int layer = blockIdx.x >> 6;
    const float* W = (layer == 0) ? W1 : ((layer == 1) ? W2 : W3);
    int idx = (blockIdx.x & 63) * 256 + threadIdx.x;
    int n = idx >> 6, kq = idx & 63;
    if (n >= 256) return;
    int k = kq * 4;
    __half2 pA = __floats2half2_rn(W[(size_t)(k+0)*CC + n], W[(size_t)(k+1)*CC + n]);
    __half2 pB = __floats2half2_rn(W[(size_t)(k+2)*CC + n], W[(size_t)(k+3)*CC + n]);
    uint2 pk; pk.x = *(uint32_t*)&pA; pk.y = *(uint32_t*)&pB;
    int nh = n >> 7, ni = n & 127, chunk = k >> 5, kin = k & 31;
    size_t eo = (size_t)layer*65536 + (size_t)(nh*8 + chunk)*4096 + swz_elem(ni, kin);
    *(uint2*)(g_bh + eo) = pk;
}

// ---------------- persistent HMMA GEMM: Him = Aimg @ W, all fp16 single ----------------
// grid (148): each CTA loops tiles bid, bid+148, ... CTA tile 128x256, 512 thr =
// 16 warps (4m x 4n), warp tile 32x64. dyn smem: 4 stages x 24KB {A 8K | B 16K}.
// Output written as fp16 directly into image layout.
#define GSTAGE 24576
#define GSM (4*GSTAGE)
__global__ __launch_bounds__(512) void k_gemm_mma(const __half* __restrict__ Aimg,
                                                  const __half* __restrict__ Bimg,
                                                  __half* __restrict__ Him) {
    extern __shared__ __align__(128) char smc[];
    uint32_t sb = smem_u32(smc);
    int tid = threadIdx.x, wid = tid >> 5, lane = tid & 31;
    int bid = blockIdx.x;
    int mwarp = (wid >> 2) * 32, nwarp = (wid & 3) * 64;

    int nt = (MTILES - bid + NSM - 1) / NSM;
    int total = nt * 8;

    const char* gA = (const char*)Aimg;
    const char* gB = (const char*)Bimg;

    int r15 = lane & 15, hi2 = lane >> 4;
    uint32_t aoff[2]; int asw[2];
    #pragma unroll
    for (int i = 0; i < 2; i++) {
        int mr = mwarp + i*16 + r15;
        aoff[i] = mr * 64; asw[i] = (mr >> 1) & 3;
    }
    uint32_t boff[4]; int bsw[4];
    uint32_t nhbase = (uint32_t)(nwarp >> 7) * 8192;
    #pragma unroll
    for (int j = 0; j < 4; j++) {
        int nr = (nwarp & 127) + j*16 + r15;
        boff[j] = nhbase + nr * 64; bsw[j] = (nr >> 1) & 3;
    }

    float d[2][8][4];
    #pragma unroll
    for (int i = 0; i < 2; i++)
        #pragma unroll
        for (int j = 0; j < 8; j++)
            #pragma unroll
            for (int q = 0; q < 4; q++) d[i][j][q] = 0.f;

    // issue chunk g: tile = bid + (g>>3)*148, chunk c = g&7, buffer g&3
    // per thread 16B x3: A 8K, B nh0 8K, B nh1 8K
    #define ISSUEG(g) do { \
        int _c = (g) & 7; \
        size_t _tb = (size_t)(bid + ((g) >> 3) * NSM) * 65536 + (size_t)_c * 8192; \
        uint32_t so = sb + (uint32_t)((g) & 3) * GSTAGE; \
        uint32_t off = (uint32_t)tid * 16; \
        CPASYNC16(so + off, gA + _tb + off); \
        _Pragma("unroll") \
        for (int nh_ = 0; nh_ < 2; nh_++) { \
            size_t gb = (size_t)(nh_*8 + _c) * 8192; \
            CPASYNC16(so + 8192 + nh_*8192 + off, gB + gb + off); \
        } \
        CPCOMMIT(); \
    } while (0)

    ISSUEG(0);
    if (total > 1) ISSUEG(1);
    if (total > 2) ISSUEG(2);
    for (int g = 0; g < total; g++) {
        int rem = total - g - 1;
        if (rem >= 2)      { CPWAIT(2); }
        else if (rem == 1) { CPWAIT(1); }
        else               { CPWAIT(0); }
        __syncthreads();
        uint32_t base = sb + (uint32_t)(g & 3) * GSTAGE;
        #pragma unroll
        for (int s = 0; s < 2; s++) {
            uint32_t ah[2][4];
            #pragma unroll
            for (int i = 0; i < 2; i++) {
                uint32_t kc = (uint32_t)((((s<<1)|hi2) ^ asw[i]) << 4);
                LDSM4(ah[i][0],ah[i][1],ah[i][2],ah[i][3], base + aoff[i] + kc);
            }
            #pragma unroll
            for (int jp = 0; jp < 2; jp++) {
                uint32_t bf[2][4];
                #pragma unroll
                for (int q = 0; q < 2; q++) {
                    int j = jp*2 + q;
                    uint32_t kc = (uint32_t)((((s<<1)|hi2) ^ bsw[j]) << 4);
                    LDSM4(bf[q][0],bf[q][1],bf[q][2],bf[q][3], base + 8192 + boff[j] + kc);
                }
                #pragma unroll
                for (int q = 0; q < 2; q++)
                    #pragma unroll
                    for (int i = 0; i < 2; i++) {
                        MMA16816(d[i][4*jp+2*q],   ah[i], bf[q][0], bf[q][2]);
                        MMA16816(d[i][4*jp+2*q+1], ah[i], bf[q][1], bf[q][3]);
                    }
            }
        }
        if (g + 3 < total) ISSUEG(g+3);
        if ((g & 7) == 7) {
            // epilogue: write fp16 image (overlaps next tile's in-flight cp.async)
            int tile = bid + (g >> 3) * NSM;
            int rr = lane >> 2, cp = (lane & 3) * 2;
            size_t tbase = (size_t)tile * 8 * 4096;
            #pragma unroll
            for (int i = 0; i < 2; i++) {
                int mr = mwarp + i*16 + rr;          // local rows mr, mr+8
                #pragma unroll
                for (int j = 0; j < 8; j++) {
                    int col = nwarp + j*8 + cp;
                    int chunk = col >> 5, kin = col & 31;
                    __half2 v01 = __floats2half2_rn(d[i][j][0], d[i][j][1]);
                    __half2 v23 = __floats2half2_rn(d[i][j][2], d[i][j][3]);
                    *(__half2*)(Him + tbase + (size_t)chunk*4096 + swz_elem(mr,   kin)) = v01;
                    *(__half2*)(Him + tbase + (size_t)chunk*4096 + swz_elem(mr+8, kin)) = v23;
                }
            }
            #pragma unroll
            for (int i = 0; i < 2; i++)
                #pragma unroll
                for (int j = 0; j < 8; j++)
                    #pragma unroll
                    for (int q = 0; q < 4; q++) d[i][j][q] = 0.f;
        }
    }
}

// ---------------- aggregation (image-layout fp16 in, fp16 image or fp32 out) ----------------
// acc = sum_in-edges norm*h[b,src,:] + dinv^2*h[b,n,:] + bias (+res), relu.
// 32-lane groups (8 ch/lane), 8 batches per block (metadata L1-broadcast).
__global__ __launch_bounds__(256) void k_agg(const __half* __restrict__ Him, int set,
                                             const float* __restrict__ bias,
                                             const float* __restrict__ residual,
                                             float* __restrict__ out,
                                             __half* __restrict__ Aimg) {
    int g    = threadIdx.x >> 5;           // batch sub-group 0..7
    int lane = threadIdx.x & 31;           // channel/8
    int n = blockIdx.x;
    int b = blockIdx.y * 8 + g;
    int ch = lane * 8;

    const int* ptr = g_ptr + set*(NN+1);
    int p0 = __ldg(&ptr[n]), p1 = __ldg(&ptr[n+1]);
    float dn = __ldg(&g_dinv[set*NN + n]);
    int bbase = b * NN;
    int m = bbase + n;

    float v[8], acc[8];
    unpack8h(*(const uint4*)(Him + img_off(m, ch)), v);
    float w = dn * dn;
    #pragma unroll
    for (int e = 0; e < 8; e++) acc[e] = w * v[e];

    int off = set*MAXE;
    int j = p0;
    for (; j + 2 <= p1; j += 2) {
        int   s0 = __ldg(&g_esrc [off + j]);
        int   s1 = __ldg(&g_esrc [off + j + 1]);
        float w0 = __ldg(&g_enorm[off + j]);
        float w1 = __ldg(&g_enorm[off + j + 1]);
        uint4 p0k = *(const uint4*)(Him + img_off(bbase + s0, ch));
        uint4 p1k = *(const uint4*)(Him + img_off(bbase + s1, ch));
        float u0[8], u1[8];
        unpack8h(p0k, u0); unpack8h(p1k, u1);
        #pragma unroll
        for (int e = 0; e < 8; e++) acc[e] += w0*u0[e] + w1*u1[e];
    }
    if (j < p1) {
        int   s0 = __ldg(&g_esrc [off + j]);
        float w0 = __ldg(&g_enorm[off + j]);
        float u0[8];
        unpack8h(*(const uint4*)(Him + img_off(bbase + s0, ch)), u0);
        #pragma unroll
        for (int e = 0; e < 8; e++) acc[e] += w0*u0[e];
    }

    float4 bi0 = *(const float4*)&bias[ch];
    float4 bi1 = *(const float4*)&bias[ch + 4];
    acc[0]+=bi0.x; acc[1]+=bi0.y; acc[2]+=bi0.z; acc[3]+=bi0.w;
    acc[4]+=bi1.x; acc[5]+=bi1.y; acc[6]+=bi1.z; acc[7]+=bi1.w;
    if (residual) {
        size_t rb = (size_t)m * CC + ch;
        float4 r0 = *(const float4*)&residual[rb];
        float4 r1 = *(const float4*)&residual[rb + 4];
        acc[0]+=r0.x; acc[1]+=r0.y; acc[2]+=r0.z; acc[3]+=r0.w;
        acc[4]+=r1.x; acc[5]+=r1.y; acc[6]+=r1.z; acc[7]+=r1.w;
    }
    #pragma unroll
    for (int e = 0; e < 8; e++) acc[e] = fmaxf(acc[e], 0.f);

    if (Aimg) {
        *(uint4*)(Aimg + img_off(m, ch)) = pack8h(acc);
    } else {
        size_t ob = (size_t)m * CC + ch;
        *(float4*)&out[ob]     = make_float4(acc[0], acc[1], acc[2], acc[3]);
        *(float4*)&out[ob + 4] = make_float4(acc[4], acc[5], acc[6], acc[7]);
    }
}

// ---------------- launch ----------------
extern "C" void kernel_launch(void* const* d_in, const int* in_sizes, int n_in,
                              void* d_out, int out_size) {
    const float* x  = (const float*)d_in[0];
    const float* W1 = (const float*)d_in[1];
    const float* b1 = (const float*)d_in[2];
    const float* W2 = (const float*)d_in[3];
    const float* b2 = (const float*)d_in[4];
    const float* W3 = (const float*)d_in[5];
    const float* b3 = (const float*)d_in[6];
    const int*   sp = (const int*)d_in[7];
    const int*   tm = (const int*)d_in[8];
    int Esp = in_sizes[7] / 2;
    int Etm = in_sizes[8] / 2;
    float* out = (float*)d_out;

    __half *ax, *hx, *bh;
    cudaGetSymbolAddress((void**)&ax, g_ax);
    cudaGetSymbolAddress((void**)&hx, g_hx);
    cudaGetSymbolAddress((void**)&bh, g_bh);

    cudaFuncSetAttribute(k_gemm_mma, cudaFuncAttributeMaxDynamicSharedMemorySize, GSM);

    dim3 ga(NN, BB/8);                // (1700, 8)

    k_convA <<<(MTOT*32 + 255)/256, 256>>>(x);
    k_convW3<<<192, 256>>>(W1, W2, W3);
    k_prep  <<<1, 1024>>>(sp, Esp, tm, Etm);

    // conv1 (4th launch — profiled by ncu)
    k_gemm_mma<<<NSM, 512, GSM>>>(ax, bh, hx);
    k_agg<<<ga, 256>>>(hx, 0, b1, nullptr, nullptr, ax);
    // conv2
    k_gemm_mma<<<NSM, 512, GSM>>>(ax, bh + 65536, hx);
    k_agg<<<ga, 256>>>(hx, 1, b2, nullptr, nullptr, ax);
    // conv3
    k_gemm_mma<<<NSM, 512, GSM>>>(ax, bh + 2*65536, hx);
    k_agg<<<ga, 256>>>(hx, 0, b3, x, out, nullptr);
}

// round 12
// speedup vs baseline: 3.1943x; 1.0268x over previous
#include <cuda_runtime.h>
#include <cuda_fp16.h>
#include <cstdint>

typedef unsigned long long ull;

#define BB 64
#define NN 1700
#define CC 256
#define MAXE 16384
#define MTOT (BB*NN)
#define MTILES (MTOT/128)          // 850
#define NHT (MTILES*2)             // 1700 half-tiles (128x128)
#define NSM2 296                   // 2 CTAs per SM

// ---------------- scratch (device globals; no allocation allowed) ----------------
__device__ __half g_ax[(size_t)MTOT*CC];           // A input images (fp16, chunked+swizzled)
__device__ __half g_hx[(size_t)MTOT*CC];           // H output images (fp16, same layout)
__device__ __half g_bh[3*65536];                   // B fp16 images per layer
__device__ int   g_ptr[2*(NN+1)];
__device__ float g_dinv[2*NN];
__device__ int   g_esrc[2*MAXE];
__device__ float g_enorm[2*MAXE];

// ---------------- PTX helpers (all sm_80-class: valid for compute_103) ----------------
__device__ __forceinline__ uint32_t smem_u32(const void* p) {
    uint32_t a;
    asm("{ .reg .u64 t; cvta.to.shared.u64 t, %1; cvt.u32.u64 %0, t; }" : "=r"(a) : "l"(p));
    return a;
}
#define LDSM4(r0,r1,r2,r3,addr) \
    asm volatile("ldmatrix.sync.aligned.m8n8.x4.shared.b16 {%0,%1,%2,%3}, [%4];" \
        : "=r"(r0),"=r"(r1),"=r"(r2),"=r"(r3) : "r"(addr))
#define MMA16816(d, a, b0, b1) \
    asm volatile("mma.sync.aligned.m16n8k16.row.col.f32.f16.f16.f32 " \
        "{%0,%1,%2,%3},{%4,%5,%6,%7},{%8,%9},{%0,%1,%2,%3};" \
        : "+f"((d)[0]),"+f"((d)[1]),"+f"((d)[2]),"+f"((d)[3]) \
        : "r"((a)[0]),"r"((a)[1]),"r"((a)[2]),"r"((a)[3]), "r"(b0),"r"(b1))
#define CPASYNC16(dst, src) \
    asm volatile("cp.async.cg.shared.global [%0], [%1], 16;" :: "r"(dst), "l"(src))
#define CPCOMMIT() asm volatile("cp.async.commit_group;")
#define CPWAIT(n)  asm volatile("cp.async.wait_group %0;" :: "n"(n))

// chunked image element offset within a 128x32 block (64B rows), 16B-chunk XOR swizzle
__device__ __forceinline__ uint32_t swz_elem(int r, int kin) {
    return (uint32_t)(r*32 + ((((kin>>3) ^ ((r>>1)&3)))<<3) + (kin&7));
}
// full image element offset for row m (0..MTOT), channel ch (0..255)
__device__ __forceinline__ size_t img_off(int m, int ch) {
    int tile = m >> 7, mi = m & 127, chunk = ch >> 5, kin = ch & 31;
    return (size_t)(tile*8 + chunk)*4096 + swz_elem(mi, kin);
}

// ---------------- fused prep: histogram -> scan -> dinv -> CSR fill, both edge sets ----------------
__global__ __launch_bounds__(1024) void k_prep(const int* __restrict__ sp, int Esp,
                                               const int* __restrict__ tm, int Etm) {
    __shared__ int   cnt[2*NN];
    __shared__ float dv [2*NN];
    __shared__ int   sbuf[2048];
    int t = threadIdx.x;
    for (int i = t; i < 2*NN; i += 1024) cnt[i] = 0;
    __syncthreads();
    const int* spc = sp + Esp;
    const int* tmc = tm + Etm;
    for (int e = t; e < Esp; e += 1024) atomicAdd(&cnt[spc[e]], 1);
    for (int e = t; e < Etm; e += 1024) atomicAdd(&cnt[NN + tmc[e]], 1);
    __syncthreads();
    for (int i = t; i < 2*NN; i += 1024) {
        float d = rsqrtf((float)(cnt[i] + 1));
        dv[i] = d; g_dinv[i] = d;
    }
    for (int set = 0; set < 2; set++) {
        __syncthreads();
        for (int i = t; i < 2048; i += 1024) sbuf[i] = (i < NN) ? cnt[set*NN + i] : 0;
        __syncthreads();
        for (int off = 1; off < 2048; off <<= 1) {
            int v0 = (t >= off) ? sbuf[t - off] : 0;
            int i1 = t + 1024;
            int v1 = sbuf[i1 - off];
            __syncthreads();
            sbuf[t] += v0; sbuf[i1] += v1;
            __syncthreads();
        }
        int* ptr = g_ptr + set*(NN+1);
        for (int i = t; i <= NN; i += 1024) ptr[i] = (i == 0) ? 0 : sbuf[i-1];
    }
    __syncthreads();
    for (int i = t; i < 2*NN; i += 1024) cnt[i] = 0;
    __syncthreads();
    for (int e = t; e < Esp; e += 1024) {
        int r = sp[e], c = spc[e];
        float nrm = dv[r] * dv[c];
        int pos = g_ptr[c] + atomicAdd(&cnt[c], 1);
        g_esrc[pos] = r; g_enorm[pos] = nrm;
    }
    for (int e = t; e < Etm; e += 1024) {
        int r = tm[e], c = tmc[e];
        float nrm = dv[NN + r] * dv[NN + c];
        int pos = g_ptr[(NN+1) + c] + atomicAdd(&cnt[NN + c], 1);
        g_esrc[MAXE + pos] = r; g_enorm[MAXE + pos] = nrm;
    }
}

// ---------------- pack/unpack helpers ----------------
__device__ __forceinline__ uint4 pack8h(const float* v) {
    __half2 p0 = __floats2half2_rn(v[0], v[1]);
    __half2 p1 = __floats2half2_rn(v[2], v[3]);
    __half2 p2 = __floats2half2_rn(v[4], v[5]);
    __half2 p3 = __floats2half2_rn(v[6], v[7]);
    uint4 r;
    r.x = *(uint32_t*)&p0; r.y = *(uint32_t*)&p1;
    r.z = *(uint32_t*)&p2; r.w = *(uint32_t*)&p3;
    return r;
}
__device__ __forceinline__ void unpack8h(uint4 p, float* v) {
    float2 f0 = __half22float2(*(__half2*)&p.x);
    float2 f1 = __half22float2(*(__half2*)&p.y);
    float2 f2 = __half22float2(*(__half2*)&p.z);
    float2 f3 = __half22float2(*(__half2*)&p.w);
    v[0]=f0.x; v[1]=f0.y; v[2]=f1.x; v[3]=f1.y;
    v[4]=f2.x; v[5]=f2.y; v[6]=f3.x; v[7]=f3.y;
}

// x fp32 [M,256] -> fp16 A image; 32 threads per row (8 ch each)
__global__ __launch_bounds__(256) void k_convA(const float* __restrict__ X) {
    int idx = blockIdx.x * 256 + threadIdx.x;
    int m = idx >> 5, lane = idx & 31;
    if (m >= MTOT) return;
    int ch = lane * 8;
    float v[8];
    *(float4*)&v[0] = *(const float4*)&X[(size_t)m * CC + ch];
    *(float4*)&v[4] = *(const float4*)&X[(size_t)m * CC + ch + 4];
    *(uint4*)(g_ax + img_off(m, ch)) = pack8h(v);
}

// all three W fp32 [k=256][n=256] -> single fp16 images (layer = blockIdx.x/64)
__global__ __launch_bounds__(256) void k_convW3(const float* __restrict__ W1,
                                                const float* __restrict__ W2,
                                                const float* __restrict__ W3) {
    int layer = blockIdx.x >> 6;
    const float* W = (layer == 0) ? W1 : ((layer == 1) ? W2 : W3);
    int idx = (blockIdx.x & 63) * 256 + threadIdx.x;
    int n = idx >> 6, kq = idx & 63;
    if (n >= 256) return;
    int k = kq * 4;
    __half2 pA = __floats2half2_rn(W[(size_t)(k+0)*CC + n], W[(size_t)(k+1)*CC + n]);
    __half2 pB = __floats2half2_rn(W[(size_t)(k+2)*CC + n], W[(size_t)(k+3)*CC + n]);
    uint2 pk; pk.x = *(uint32_t*)&pA; pk.y = *(uint32_t*)&pB;
    int nh = n >> 7, ni = n & 127, chunk = k >> 5, kin = k & 31;
    size_t eo = (size_t)layer*65536 + (size_t)(nh*8 + chunk)*4096 + swz_elem(ni, kin);
    *(uint2*)(g_bh + eo) = pk;
}

// ---------------- persistent HMMA GEMM (2 CTAs/SM): Him = Aimg @ W, fp16 ----------------
// grid (296): each CTA loops half-tiles (128x128). 256 thr = 8 warps (4m x 2n),
// warp tile 32x64. dyn smem: 4 stages x 16KB {A 8K | B 8K}.
#define GSTAGE 16384
#define GSM (4*GSTAGE)
__global__ __launch_bounds__(256, 2) void k_gemm_mma(const __half* __restrict__ Aimg,
                                                     const __half* __restrict__ Bimg,
                                                     __half* __restrict__ Him) {
    extern __shared__ __align__(128) char smc[];
    uint32_t sb = smem_u32(smc);
    int tid = threadIdx.x, wid = tid >> 5, lane = tid & 31;
    int bid = blockIdx.x;
    int mwarp = (wid >> 1) * 32, nwarp = (wid & 1) * 64;

    int nht = (NHT - bid + NSM2 - 1) / NSM2;
    int total = nht * 8;

    const char* gA = (const char*)Aimg;
    const char* gB = (const char*)Bimg;

    int r15 = lane & 15, hi2 = lane >> 4;
    uint32_t aoff[2]; int asw[2];
    #pragma unroll
    for (int i = 0; i < 2; i++) {
        int mr = mwarp + i*16 + r15;
        aoff[i] = mr * 64; asw[i] = (mr >> 1) & 3;
    }
    uint32_t boff[4]; int bsw[4];
    #pragma unroll
    for (int j = 0; j < 4; j++) {
        int nr = nwarp + j*16 + r15;
        boff[j] = nr * 64; bsw[j] = (nr >> 1) & 3;
    }

    float d[2][8][4];
    #pragma unroll
    for (int i = 0; i < 2; i++)
        #pragma unroll
        for (int j = 0; j < 8; j++)
            #pragma unroll
            for (int q = 0; q < 4; q++) d[i][j][q] = 0.f;

    // issue chunk g: ht = bid + (g>>3)*296, chunk c = g&7, buffer g&3
    #define ISSUEG(g) do { \
        int _c = (g) & 7; \
        int _ht = bid + ((g) >> 3) * NSM2; \
        int _tile = _ht >> 1, _nh = _ht & 1; \
        size_t _ab = (size_t)_tile * 65536 + (size_t)_c * 8192; \
        size_t _bb = (size_t)(_nh*8 + _c) * 8192; \
        uint32_t so = sb + (uint32_t)((g) & 3) * GSTAGE; \
        uint32_t off = (uint32_t)tid * 16; \
        CPASYNC16(so + off,          gA + _ab + off); \
        CPASYNC16(so + off + 4096,   gA + _ab + off + 4096); \
        CPASYNC16(so + 8192 + off,        gB + _bb + off); \
        CPASYNC16(so + 8192 + off + 4096, gB + _bb + off + 4096); \
        CPCOMMIT(); \
    } while (0)

    ISSUEG(0);
    if (total > 1) ISSUEG(1);
    if (total > 2) ISSUEG(2);
    for (int g = 0; g < total; g++) {
        int rem = total - g - 1;
        if (rem >= 2)      { CPWAIT(2); }
        else if (rem == 1) { CPWAIT(1); }
        else               { CPWAIT(0); }
        __syncthreads();
        uint32_t base = sb + (uint32_t)(g & 3) * GSTAGE;
        #pragma unroll
        for (int s = 0; s < 2; s++) {
            uint32_t ah[2][4];
            #pragma unroll
            for (int i = 0; i < 2; i++) {
                uint32_t kc = (uint32_t)((((s<<1)|hi2) ^ asw[i]) << 4);
                LDSM4(ah[i][0],ah[i][1],ah[i][2],ah[i][3], base + aoff[i] + kc);
            }
            #pragma unroll
            for (int jp = 0; jp < 2; jp++) {
                uint32_t bf[2][4];
                #pragma unroll
                for (int q = 0; q < 2; q++) {
                    int j = jp*2 + q;
                    uint32_t kc = (uint32_t)((((s<<1)|hi2) ^ bsw[j]) << 4);
                    LDSM4(bf[q][0],bf[q][1],bf[q][2],bf[q][3], base + 8192 + boff[j] + kc);
                }
                #pragma unroll
                for (int q = 0; q < 2; q++)
                    #pragma unroll
                    for (int i = 0; i < 2; i++) {
                        MMA16816(d[i][4*jp+2*q],   ah[i], bf[q][0], bf[q][2]);
                        MMA16816(d[i][4*jp+2*q+1], ah[i], bf[q][1], bf[q][3]);
                    }
            }
        }
        if (g + 3 < total) ISSUEG(g+3);
        if ((g & 7) == 7) {
            // epilogue for finished half-tile (overlaps other CTA + next tile's loads)
            int ht = bid + (g >> 3) * NSM2;
            int tile = ht >> 1, nh = ht & 1;
            int rr = lane >> 2, cp = (lane & 3) * 2;
            size_t tbase = (size_t)tile * 8 * 4096;
            #pragma unroll
            for (int i = 0; i < 2; i++) {
                int mr = mwarp + i*16 + rr;
                #pragma unroll
                for (int j = 0; j < 8; j++) {
                    int col = nh*128 + nwarp + j*8 + cp;
                    int chunk = col >> 5, kin = col & 31;
                    __half2 v01 = __floats2half2_rn(d[i][j][0], d[i][j][1]);
                    __half2 v23 = __floats2half2_rn(d[i][j][2], d[i][j][3]);
                    *(__half2*)(Him + tbase + (size_t)chunk*4096 + swz_elem(mr,   kin)) = v01;
                    *(__half2*)(Him + tbase + (size_t)chunk*4096 + swz_elem(mr+8, kin)) = v23;
                }
            }
            #pragma unroll
            for (int i = 0; i < 2; i++)
                #pragma unroll
                for (int j = 0; j < 8; j++)
                    #pragma unroll
                    for (int q = 0; q < 4; q++) d[i][j][q] = 0.f;
        }
    }
}

// ---------------- aggregation (image-layout fp16 in, fp16 image or fp32 out) ----------------
// acc = sum_in-edges norm*h[b,src,:] + dinv^2*h[b,n,:] + bias (+res), relu.
// 32-lane groups (8 ch/lane), 8 batches per block; 4-edge unroll, gathers batched for MLP.
__global__ __launch_bounds__(256) void k_agg(const __half* __restrict__ Him, int set,
                                             const float* __restrict__ bias,
                                             const float* __restrict__ residual,
                                             float* __restrict__ out,
                                             __half* __restrict__ Aimg) {
    int g    = threadIdx.x >> 5;           // batch sub-group 0..7
    int lane = threadIdx.x & 31;           // channel/8
    int n = blockIdx.x;
    int b = blockIdx.y * 8 + g;
    int ch = lane * 8;

    const int* ptr = g_ptr + set*(NN+1);
    int p0 = __ldg(&ptr[n]), p1 = __ldg(&ptr[n+1]);
    float dn = __ldg(&g_dinv[set*NN + n]);
    int bbase = b * NN;
    int m = bbase + n;

    float v[8], acc[8];
    unpack8h(*(const uint4*)(Him + img_off(m, ch)), v);
    float w = dn * dn;
    #pragma unroll
    for (int e = 0; e < 8; e++) acc[e] = w * v[e];

    int off = set*MAXE;
    int j = p0;
    for (; j + 4 <= p1; j += 4) {
        int   s0 = __ldg(&g_esrc [off + j]);
        int   s1 = __ldg(&g_esrc [off + j + 1]);
        int   s2 = __ldg(&g_esrc [off + j + 2]);
        int   s3 = __ldg(&g_esrc [off + j + 3]);
        float w0 = __ldg(&g_enorm[off + j]);
        float w1 = __ldg(&g_enorm[off + j + 1]);
        float w2 = __ldg(&g_enorm[off + j + 2]);
        float w3 = __ldg(&g_enorm[off + j + 3]);
        // batch all gathers before any unpack (MLP=4)
        uint4 pk0 = *(const uint4*)(Him + img_off(bbase + s0, ch));
        uint4 pk1 = *(const uint4*)(Him + img_off(bbase + s1, ch));
        uint4 pk2 = *(const uint4*)(Him + img_off(bbase + s2, ch));
        uint4 pk3 = *(const uint4*)(Him + img_off(bbase + s3, ch));
        float u0[8], u1[8], u2[8], u3[8];
        unpack8h(pk0, u0); unpack8h(pk1, u1);
        unpack8h(pk2, u2); unpack8h(pk3, u3);
        #pragma unroll
        for (int e = 0; e < 8; e++)
            acc[e] += w0*u0[e] + w1*u1[e] + w2*u2[e] + w3*u3[e];
    }
    if (j + 2 <= p1) {
        int   s0 = __ldg(&g_esrc [off + j]);
        int   s1 = __ldg(&g_esrc [off + j + 1]);
        float w0 = __ldg(&g_enorm[off + j]);
        float w1 = __ldg(&g_enorm[off + j + 1]);
        uint4 pk0 = *(const uint4*)(Him + img_off(bbase + s0, ch));
        uint4 pk1 = *(const uint4*)(Him + img_off(bbase + s1, ch));
        float u0[8], u1[8];
        unpack8h(pk0, u0); unpack8h(pk1, u1);
        #pragma unroll
        for (int e = 0; e < 8; e++) acc[e] += w0*u0[e] + w1*u1[e];
        j += 2;
    }
    if (j < p1) {
        int   s0 = __ldg(&g_esrc [off + j]);
        float w0 = __ldg(&g_enorm[off + j]);
        float u0[8];
        unpack8h(*(const uint4*)(Him + img_off(bbase + s0, ch)), u0);
        #pragma unroll
        for (int e = 0; e < 8; e++) acc[e] += w0*u0[e];
    }

    float4 bi0 = *(const float4*)&bias[ch];
    float4 bi1 = *(const float4*)&bias[ch + 4];
    acc[0]+=bi0.x; acc[1]+=bi0.y; acc[2]+=bi0.z; acc[3]+=bi0.w;
    acc[4]+=bi1.x; acc[5]+=bi1.y; acc[6]+=bi1.z; acc[7]+=bi1.w;
    if (residual) {
        size_t rb = (size_t)m * CC + ch;
        float4 r0 = *(const float4*)&residual[rb];
        float4 r1 = *(const float4*)&residual[rb + 4];
        acc[0]+=r0.x; acc[1]+=r0.y; acc[2]+=r0.z; acc[3]+=r0.w;
        acc[4]+=r1.x; acc[5]+=r1.y; acc[6]+=r1.z; acc[7]+=r1.w;
    }
    #pragma unroll
    for (int e = 0; e < 8; e++) acc[e] = fmaxf(acc[e], 0.f);

    if (Aimg) {
        *(uint4*)(Aimg + img_off(m, ch)) = pack8h(acc);
    } else {
        size_t ob = (size_t)m * CC + ch;
        *(float4*)&out[ob]     = make_float4(acc[0], acc[1], acc[2], acc[3]);
        *(float4*)&out[ob + 4] = make_float4(acc[4], acc[5], acc[6], acc[7]);
    }
}

// ---------------- launch ----------------
extern "C" void kernel_launch(void* const* d_in, const int* in_sizes, int n_in,
                              void* d_out, int out_size) {
    const float* x  = (const float*)d_in[0];
    const float* W1 = (const float*)d_in[1];
    const float* b1 = (const float*)d_in[2];
    const float* W2 = (const float*)d_in[3];
    const float* b2 = (const float*)d_in[4];
    const float* W3 = (const float*)d_in[5];
    const float* b3 = (const float*)d_in[6];
    const int*   sp = (const int*)d_in[7];
    const int*   tm = (const int*)d_in[8];
    int Esp = in_sizes[7] / 2;
    int Etm = in_sizes[8] / 2;
    float* out = (float*)d_out;

    __half *ax, *hx, *bh;
    cudaGetSymbolAddress((void**)&ax, g_ax);
    cudaGetSymbolAddress((void**)&hx, g_hx);
    cudaGetSymbolAddress((void**)&bh, g_bh);

    cudaFuncSetAttribute(k_gemm_mma, cudaFuncAttributeMaxDynamicSharedMemorySize, GSM);

    dim3 ga(NN, BB/8);                // (1700, 8)

    k_convA <<<(MTOT*32 + 255)/256, 256>>>(x);
    k_convW3<<<192, 256>>>(W1, W2, W3);
    k_prep  <<<1, 1024>>>(sp, Esp, tm, Etm);

    // conv1 (4th launch — profiled by ncu)
    k_gemm_mma<<<NSM2, 256, GSM>>>(ax, bh, hx);
    k_agg<<<ga, 256>>>(hx, 0, b1, nullptr, nullptr, ax);
    // conv2
    k_gemm_mma<<<NSM2, 256, GSM>>>(ax, bh + 65536, hx);
    k_agg<<<ga, 256>>>(hx, 1, b2, nullptr, nullptr, ax);
    // conv3
    k_gemm_mma<<<NSM2, 256, GSM>>>(ax, bh + 2*65536, hx);
    k_agg<<<ga, 256>>>(hx, 0, b3, x, out, nullptr);
}

// round 13
// speedup vs baseline: 3.2129x; 1.0058x over previous
#include <cuda_runtime.h>
#include <cuda_fp16.h>
#include <cstdint>

typedef unsigned long long ull;

#define BB 64
#define NN 1700
#define CC 256
#define MAXE 16384
#define MTOT (BB*NN)
#define MTILES (MTOT/128)          // 850
#define NHT (MTILES*2)             // 1700 half-tiles (128x128)
#define NSM2 296                   // 2 CTAs per SM

// ---------------- scratch (device globals; no allocation allowed) ----------------
__device__ __half g_ax[(size_t)MTOT*CC];           // A input images (fp16, chunked+swizzled)
__device__ __half g_hx[(size_t)MTOT*CC];           // H output images (fp16, same layout)
__device__ __half g_bh[3*65536];                   // B fp16 images per layer
__device__ int   g_ptr[2*(NN+1)];
__device__ float g_dinv[2*NN];
__device__ int   g_esrc[2*MAXE];
__device__ float g_enorm[2*MAXE];

// ---------------- PTX helpers (all sm_80-class: valid for compute_103) ----------------
__device__ __forceinline__ uint32_t smem_u32(const void* p) {
    uint32_t a;
    asm("{ .reg .u64 t; cvta.to.shared.u64 t, %1; cvt.u32.u64 %0, t; }" : "=r"(a) : "l"(p));
    return a;
}
#define LDSM4(r0,r1,r2,r3,addr) \
    asm volatile("ldmatrix.sync.aligned.m8n8.x4.shared.b16 {%0,%1,%2,%3}, [%4];" \
        : "=r"(r0),"=r"(r1),"=r"(r2),"=r"(r3) : "r"(addr))
#define MMA16816(d, a, b0, b1) \
    asm volatile("mma.sync.aligned.m16n8k16.row.col.f32.f16.f16.f32 " \
        "{%0,%1,%2,%3},{%4,%5,%6,%7},{%8,%9},{%0,%1,%2,%3};" \
        : "+f"((d)[0]),"+f"((d)[1]),"+f"((d)[2]),"+f"((d)[3]) \
        : "r"((a)[0]),"r"((a)[1]),"r"((a)[2]),"r"((a)[3]), "r"(b0),"r"(b1))
#define CPASYNC16(dst, src) \
    asm volatile("cp.async.cg.shared.global [%0], [%1], 16;" :: "r"(dst), "l"(src))
#define CPCOMMIT() asm volatile("cp.async.commit_group;")
#define CPWAIT(n)  asm volatile("cp.async.wait_group %0;" :: "n"(n))

// chunked image element offset within a 128x32 block (64B rows), 16B-chunk XOR swizzle
__device__ __forceinline__ uint32_t swz_elem(int r, int kin) {
    return (uint32_t)(r*32 + ((((kin>>3) ^ ((r>>1)&3)))<<3) + (kin&7));
}
// full image element offset for row m (0..MTOT), channel ch (0..255)
__device__ __forceinline__ size_t img_off(int m, int ch) {
    int tile = m >> 7, mi = m & 127, chunk = ch >> 5, kin = ch & 31;
    return (size_t)(tile*8 + chunk)*4096 + swz_elem(mi, kin);
}

// ---------------- fused prep: histogram -> scan -> dinv -> CSR fill, both edge sets ----------------
__global__ __launch_bounds__(1024) void k_prep(const int* __restrict__ sp, int Esp,
                                               const int* __restrict__ tm, int Etm) {
    __shared__ int   cnt[2*NN];
    __shared__ float dv [2*NN];
    __shared__ int   sbuf[2048];
    int t = threadIdx.x;
    for (int i = t; i < 2*NN; i += 1024) cnt[i] = 0;
    __syncthreads();
    const int* spc = sp + Esp;
    const int* tmc = tm + Etm;
    for (int e = t; e < Esp; e += 1024) atomicAdd(&cnt[spc[e]], 1);
    for (int e = t; e < Etm; e += 1024) atomicAdd(&cnt[NN + tmc[e]], 1);
    __syncthreads();
    for (int i = t; i < 2*NN; i += 1024) {
        float d = rsqrtf((float)(cnt[i] + 1));
        dv[i] = d; g_dinv[i] = d;
    }
    for (int set = 0; set < 2; set++) {
        __syncthreads();
        for (int i = t; i < 2048; i += 1024) sbuf[i] = (i < NN) ? cnt[set*NN + i] : 0;
        __syncthreads();
        for (int off = 1; off < 2048; off <<= 1) {
            int v0 = (t >= off) ? sbuf[t - off] : 0;
            int i1 = t + 1024;
            int v1 = sbuf[i1 - off];
            __syncthreads();
            sbuf[t] += v0; sbuf[i1] += v1;
            __syncthreads();
        }
        int* ptr = g_ptr + set*(NN+1);
        for (int i = t; i <= NN; i += 1024) ptr[i] = (i == 0) ? 0 : sbuf[i-1];
    }
    __syncthreads();
    for (int i = t; i < 2*NN; i += 1024) cnt[i] = 0;
    __syncthreads();
    for (int e = t; e < Esp; e += 1024) {
        int r = sp[e], c = spc[e];
        float nrm = dv[r] * dv[c];
        int pos = g_ptr[c] + atomicAdd(&cnt[c], 1);
        g_esrc[pos] = r; g_enorm[pos] = nrm;
    }
    for (int e = t; e < Etm; e += 1024) {
        int r = tm[e], c = tmc[e];
        float nrm = dv[NN + r] * dv[NN + c];
        int pos = g_ptr[(NN+1) + c] + atomicAdd(&cnt[NN + c], 1);
        g_esrc[MAXE + pos] = r; g_enorm[MAXE + pos] = nrm;
    }
}

// ---------------- pack/unpack helpers ----------------
__device__ __forceinline__ uint4 pack8h(const float* v) {
    __half2 p0 = __floats2half2_rn(v[0], v[1]);
    __half2 p1 = __floats2half2_rn(v[2], v[3]);
    __half2 p2 = __floats2half2_rn(v[4], v[5]);
    __half2 p3 = __floats2half2_rn(v[6], v[7]);
    uint4 r;
    r.x = *(uint32_t*)&p0; r.y = *(uint32_t*)&p1;
    r.z = *(uint32_t*)&p2; r.w = *(uint32_t*)&p3;
    return r;
}
__device__ __forceinline__ void unpack8h(uint4 p, float* v) {
    float2 f0 = __half22float2(*(__half2*)&p.x);
    float2 f1 = __half22float2(*(__half2*)&p.y);
    float2 f2 = __half22float2(*(__half2*)&p.z);
    float2 f3 = __half22float2(*(__half2*)&p.w);
    v[0]=f0.x; v[1]=f0.y; v[2]=f1.x; v[3]=f1.y;
    v[4]=f2.x; v[5]=f2.y; v[6]=f3.x; v[7]=f3.y;
}

// x fp32 [M,256] -> fp16 A image; 32 threads per row; handles rows [m0, m0+MTOT/2)
__global__ __launch_bounds__(256) void k_convA(const float* __restrict__ X, int m0) {
    int idx = blockIdx.x * 256 + threadIdx.x;
    int m = m0 + (idx >> 5), lane = idx & 31;
    if (m >= MTOT) return;
    int ch = lane * 8;
    float v[8];
    *(float4*)&v[0] = *(const float4*)&X[(size_t)m * CC + ch];
    *(float4*)&v[4] = *(const float4*)&X[(size_t)m * CC + ch + 4];
    *(uint4*)(g_ax + img_off(m, ch)) = pack8h(v);
}

// all three W fp32 [k=256][n=256] -> single fp16 images (layer = blockIdx.x/64)
__global__ __launch_bounds__(256) void k_convW3(const float* __restrict__ W1,
                                                const float* __restrict__ W2,
                                                const float* __restrict__ W3) {
    int layer = blockIdx.x >> 6;
    const float* W = (layer == 0) ? W1 : ((layer == 1) ? W2 : W3);
    int idx = (blockIdx.x & 63) * 256 + threadIdx.x;
    int n = idx >> 6, kq = idx & 63;
    if (n >= 256) return;
    int k = kq * 4;
    __half2 pA = __floats2half2_rn(W[(size_t)(k+0)*CC + n], W[(size_t)(k+1)*CC + n]);
    __half2 pB = __floats2half2_rn(W[(size_t)(k+2)*CC + n], W[(size_t)(k+3)*CC + n]);
    uint2 pk; pk.x = *(uint32_t*)&pA; pk.y = *(uint32_t*)&pB;
    int nh = n >> 7, ni = n & 127, chunk = k >> 5, kin = k & 31;
    size_t eo = (size_t)layer*65536 + (size_t)(nh*8 + chunk)*4096 + swz_elem(ni, kin);
    *(uint2*)(g_bh + eo) = pk;
}

// ---------------- persistent HMMA GEMM (2 CTAs/SM, B-resident): Him = Aimg @ W ----------------
// grid (296): CTA bid handles half-tiles bid, bid+296, ... (nh = bid&1 fixed).
// B for this nh (64KB) loaded ONCE into smem; only A streams (4 stages x 8KB).
// 256 thr = 8 warps (4m x 2n), warp tile 32x64. smem: B 64KB @0, A stages @65536.
#define ASTAGE 8192
#define GSM (65536 + 4*ASTAGE)
__global__ __launch_bounds__(256, 2) void k_gemm_mma(const __half* __restrict__ Aimg,
                                                     const __half* __restrict__ Bimg,
                                                     __half* __restrict__ Him) {
    extern __shared__ __align__(128) char smc[];
    uint32_t sb = smem_u32(smc);
    int tid = threadIdx.x, wid = tid >> 5, lane = tid & 31;
    int bid = blockIdx.x;
    int nh = bid & 1;
    int mwarp = (wid >> 1) * 32, nwarp = (wid & 1) * 64;

    int nht = (NHT - bid + NSM2 - 1) / NSM2;
    int total = nht * 8;

    const char* gA = (const char*)Aimg;
    const char* gB = (const char*)Bimg + (size_t)nh * 8 * 8192;

    // prologue: load full B half (64KB) into smem (group 0)
    {
        uint32_t off = (uint32_t)tid * 16;
        #pragma unroll
        for (int c = 0; c < 8; c++) {
            CPASYNC16(sb + c*8192 + off,        gB + (size_t)c*8192 + off);
            CPASYNC16(sb + c*8192 + off + 4096, gB + (size_t)c*8192 + off + 4096);
        }
        CPCOMMIT();
    }

    int r15 = lane & 15, hi2 = lane >> 4;
    uint32_t aoff[2]; int asw[2];
    #pragma unroll
    for (int i = 0; i < 2; i++) {
        int mr = mwarp + i*16 + r15;
        aoff[i] = mr * 64; asw[i] = (mr >> 1) & 3;
    }
    uint32_t boff[4]; int bsw[4];
    #pragma unroll
    for (int j = 0; j < 4; j++) {
        int nr = nwarp + j*16 + r15;
        boff[j] = nr * 64; bsw[j] = (nr >> 1) & 3;
    }

    float d[2][8][4];
    #pragma unroll
    for (int i = 0; i < 2; i++)
        #pragma unroll
        for (int j = 0; j < 8; j++)
            #pragma unroll
            for (int q = 0; q < 4; q++) d[i][j][q] = 0.f;

    // issue A chunk g: ht = bid + (g>>3)*296, chunk c = g&7, buffer g&3
    #define ISSUEG(g) do { \
        int _c = (g) & 7; \
        int _tile = (bid + (((g) >> 3) * NSM2)) >> 1; \
        size_t _ab = (size_t)_tile * 65536 + (size_t)_c * 8192; \
        uint32_t so = sb + 65536 + (uint32_t)((g) & 3) * ASTAGE; \
        uint32_t off = (uint32_t)tid * 16; \
        CPASYNC16(so + off,        gA + _ab + off); \
        CPASYNC16(so + off + 4096, gA + _ab + off + 4096); \
        CPCOMMIT(); \
    } while (0)

    ISSUEG(0);
    if (total > 1) ISSUEG(1);
    if (total > 2) ISSUEG(2);
    for (int g = 0; g < total; g++) {
        int rem = total - g - 1;
        if (rem >= 2)      { CPWAIT(2); }
        else if (rem == 1) { CPWAIT(1); }
        else               { CPWAIT(0); }
        __syncthreads();
        int c = g & 7;
        uint32_t abase = sb + 65536 + (uint32_t)(g & 3) * ASTAGE;
        uint32_t bbase = sb + (uint32_t)c * 8192;
        #pragma unroll
        for (int s = 0; s < 2; s++) {
            uint32_t ah[2][4];
            #pragma unroll
            for (int i = 0; i < 2; i++) {
                uint32_t kc = (uint32_t)((((s<<1)|hi2) ^ asw[i]) << 4);
                LDSM4(ah[i][0],ah[i][1],ah[i][2],ah[i][3], abase + aoff[i] + kc);
            }
            #pragma unroll
            for (int jp = 0; jp < 2; jp++) {
                uint32_t bf[2][4];
                #pragma unroll
                for (int q = 0; q < 2; q++) {
                    int j = jp*2 + q;
                    uint32_t kc = (uint32_t)((((s<<1)|hi2) ^ bsw[j]) << 4);
                    LDSM4(bf[q][0],bf[q][1],bf[q][2],bf[q][3], bbase + boff[j] + kc);
                }
                #pragma unroll
                for (int q = 0; q < 2; q++)
                    #pragma unroll
                    for (int i = 0; i < 2; i++) {
                        MMA16816(d[i][4*jp+2*q],   ah[i], bf[q][0], bf[q][2]);
                        MMA16816(d[i][4*jp+2*q+1], ah[i], bf[q][1], bf[q][3]);
                    }
            }
        }
        if (g + 3 < total) ISSUEG(g+3);
        if (c == 7) {
            // epilogue for finished half-tile (overlaps other CTA + in-flight loads)
            int tile = (bid + ((g >> 3) * NSM2)) >> 1;
            int rr = lane >> 2, cp = (lane & 3) * 2;
            size_t tbase = (size_t)tile * 8 * 4096;
            #pragma unroll
            for (int i = 0; i < 2; i++) {
                int mr = mwarp + i*16 + rr;
                #pragma unroll
                for (int j = 0; j < 8; j++) {
                    int col = nh*128 + nwarp + j*8 + cp;
                    int chunk = col >> 5, kin = col & 31;
                    __half2 v01 = __floats2half2_rn(d[i][j][0], d[i][j][1]);
                    __half2 v23 = __floats2half2_rn(d[i][j][2], d[i][j][3]);
                    *(__half2*)(Him + tbase + (size_t)chunk*4096 + swz_elem(mr,   kin)) = v01;
                    *(__half2*)(Him + tbase + (size_t)chunk*4096 + swz_elem(mr+8, kin)) = v23;
                }
            }
            #pragma unroll
            for (int i = 0; i < 2; i++)
                #pragma unroll
                for (int j = 0; j < 8; j++)
                    #pragma unroll
                    for (int q = 0; q < 4; q++) d[i][j][q] = 0.f;
        }
    }
}

// ---------------- aggregation (image-layout fp16 in, fp16 image or fp32 out) ----------------
// acc = sum_in-edges norm*h[b,src,:] + dinv^2*h[b,n,:] + bias (+res), relu.
// 32-lane groups (8 ch/lane), 8 batches per block; 4-edge unroll, gathers batched for MLP.
__global__ __launch_bounds__(256) void k_agg(const __half* __restrict__ Him, int set,
                                             const float* __restrict__ bias,
                                             const float* __restrict__ residual,
                                             float* __restrict__ out,
                                             __half* __restrict__ Aimg) {
    int g    = threadIdx.x >> 5;           // batch sub-group 0..7
    int lane = threadIdx.x & 31;           // channel/8
    int n = blockIdx.x;
    int b = blockIdx.y * 8 + g;
    int ch = lane * 8;

    const int* ptr = g_ptr + set*(NN+1);
    int p0 = __ldg(&ptr[n]), p1 = __ldg(&ptr[n+1]);
    float dn = __ldg(&g_dinv[set*NN + n]);
    int bbase = b * NN;
    int m = bbase + n;

    float v[8], acc[8];
    unpack8h(*(const uint4*)(Him + img_off(m, ch)), v);
    float w = dn * dn;
    #pragma unroll
    for (int e = 0; e < 8; e++) acc[e] = w * v[e];

    int off = set*MAXE;
    int j = p0;
    for (; j + 4 <= p1; j += 4) {
        int   s0 = __ldg(&g_esrc [off + j]);
        int   s1 = __ldg(&g_esrc [off + j + 1]);
        int   s2 = __ldg(&g_esrc [off + j + 2]);
        int   s3 = __ldg(&g_esrc [off + j + 3]);
        float w0 = __ldg(&g_enorm[off + j]);
        float w1 = __ldg(&g_enorm[off + j + 1]);
        float w2 = __ldg(&g_enorm[off + j + 2]);
        float w3 = __ldg(&g_enorm[off + j + 3]);
        uint4 pk0 = *(const uint4*)(Him + img_off(bbase + s0, ch));
        uint4 pk1 = *(const uint4*)(Him + img_off(bbase + s1, ch));
        uint4 pk2 = *(const uint4*)(Him + img_off(bbase + s2, ch));
        uint4 pk3 = *(const uint4*)(Him + img_off(bbase + s3, ch));
        float u0[8], u1[8], u2[8], u3[8];
        unpack8h(pk0, u0); unpack8h(pk1, u1);
        unpack8h(pk2, u2); unpack8h(pk3, u3);
        #pragma unroll
        for (int e = 0; e < 8; e++)
            acc[e] += w0*u0[e] + w1*u1[e] + w2*u2[e] + w3*u3[e];
    }
    if (j + 2 <= p1) {
        int   s0 = __ldg(&g_esrc [off + j]);
        int   s1 = __ldg(&g_esrc [off + j + 1]);
        float w0 = __ldg(&g_enorm[off + j]);
        float w1 = __ldg(&g_enorm[off + j + 1]);
        uint4 pk0 = *(const uint4*)(Him + img_off(bbase + s0, ch));
        uint4 pk1 = *(const uint4*)(Him + img_off(bbase + s1, ch));
        float u0[8], u1[8];
        unpack8h(pk0, u0); unpack8h(pk1, u1);
        #pragma unroll
        for (int e = 0; e < 8; e++) acc[e] += w0*u0[e] + w1*u1[e];
        j += 2;
    }
    if (j < p1) {
        int   s0 = __ldg(&g_esrc [off + j]);
        float w0 = __ldg(&g_enorm[off + j]);
        float u0[8];
        unpack8h(*(const uint4*)(Him + img_off(bbase + s0, ch)), u0);
        #pragma unroll
        for (int e = 0; e < 8; e++) acc[e] += w0*u0[e];
    }

    float4 bi0 = *(const float4*)&bias[ch];
    float4 bi1 = *(const float4*)&bias[ch + 4];
    acc[0]+=bi0.x; acc[1]+=bi0.y; acc[2]+=bi0.z; acc[3]+=bi0.w;
    acc[4]+=bi1.x; acc[5]+=bi1.y; acc[6]+=bi1.z; acc[7]+=bi1.w;
    if (residual) {
        size_t rb = (size_t)m * CC + ch;
        float4 r0 = *(const float4*)&residual[rb];
        float4 r1 = *(const float4*)&residual[rb + 4];
        acc[0]+=r0.x; acc[1]+=r0.y; acc[2]+=r0.z; acc[3]+=r0.w;
        acc[4]+=r1.x; acc[5]+=r1.y; acc[6]+=r1.z; acc[7]+=r1.w;
    }
    #pragma unroll
    for (int e = 0; e < 8; e++) acc[e] = fmaxf(acc[e], 0.f);

    if (Aimg) {
        *(uint4*)(Aimg + img_off(m, ch)) = pack8h(acc);
    } else {
        size_t ob = (size_t)m * CC + ch;
        *(float4*)&out[ob]     = make_float4(acc[0], acc[1], acc[2], acc[3]);
        *(float4*)&out[ob + 4] = make_float4(acc[4], acc[5], acc[6], acc[7]);
    }
}

// ---------------- launch ----------------
extern "C" void kernel_launch(void* const* d_in, const int* in_sizes, int n_in,
                              void* d_out, int out_size) {
    const float* x  = (const float*)d_in[0];
    const float* W1 = (const float*)d_in[1];
    const float* b1 = (const float*)d_in[2];
    const float* W2 = (const float*)d_in[3];
    const float* b2 = (const float*)d_in[4];
    const float* W3 = (const float*)d_in[5];
    const float* b3 = (const float*)d_in[6];
    const int*   sp = (const int*)d_in[7];
    const int*   tm = (const int*)d_in[8];
    int Esp = in_sizes[7] / 2;
    int Etm = in_sizes[8] / 2;
    float* out = (float*)d_out;

    __half *ax, *hx, *bh;
    cudaGetSymbolAddress((void**)&ax, g_ax);
    cudaGetSymbolAddress((void**)&hx, g_hx);
    cudaGetSymbolAddress((void**)&bh, g_bh);

    cudaFuncSetAttribute(k_gemm_mma, cudaFuncAttributeMaxDynamicSharedMemorySize, GSM);

    dim3 ga(NN, BB/8);                // (1700, 8)
    int convg = ((MTOT/2)*32 + 255)/256;

    // launches 1-5, so agg1 is launch #6 (the one ncu -s 5 -c 1 captures)
    k_convA <<<convg, 256>>>(x, 0);
    k_convA <<<convg, 256>>>(x, MTOT/2);
    k_convW3<<<192, 256>>>(W1, W2, W3);
    k_prep  <<<1, 1024>>>(sp, Esp, tm, Etm);

    // conv1
    k_gemm_mma<<<NSM2, 256, GSM>>>(ax, bh, hx);
    k_agg<<<ga, 256>>>(hx, 0, b1, nullptr, nullptr, ax);   // launch #6 — profiled
    // conv2
    k_gemm_mma<<<NSM2, 256, GSM>>>(ax, bh + 65536, hx);
    k_agg<<<ga, 256>>>(hx, 1, b2, nullptr, nullptr, ax);
    // conv3
    k_gemm_mma<<<NSM2, 256, GSM>>>(ax, bh + 2*65536, hx);
    k_agg<<<ga, 256>>>(hx, 0, b3, x, out, nullptr);
}

// round 14
// speedup vs baseline: 3.3657x; 1.0476x over previous
#include <cuda_runtime.h>
#include <cuda_fp16.h>
#include <cstdint>

typedef unsigned long long ull;

#define BB 64
#define NN 1700
#define CC 256
#define MAXE 16384
#define MTOT (BB*NN)
#define MTILES (MTOT/128)          // 850
#define NHT (MTILES*2)             // 1700 half-tiles (128x128)
#define NSM2 296                   // 2 CTAs per SM

// ---------------- scratch (device globals; no allocation allowed) ----------------
__device__ __half g_ax[(size_t)MTOT*CC];           // A input images (fp16, chunked+swizzled)
__device__ __half g_hx[(size_t)MTOT*CC];           // H output images (fp16, same layout)
__device__ __half g_bh[3*65536];                   // B fp16 images per layer
__device__ int   g_ptr[2*(NN+1)];
__device__ float g_dinv[2*NN];
__device__ int   g_esrc[2*MAXE];
__device__ float g_enorm[2*MAXE];

// ---------------- PTX helpers (all sm_80-class: valid for compute_103) ----------------
__device__ __forceinline__ uint32_t smem_u32(const void* p) {
    uint32_t a;
    asm("{ .reg .u64 t; cvta.to.shared.u64 t, %1; cvt.u32.u64 %0, t; }" : "=r"(a) : "l"(p));
    return a;
}
#define LDSM4(r0,r1,r2,r3,addr) \
    asm volatile("ldmatrix.sync.aligned.m8n8.x4.shared.b16 {%0,%1,%2,%3}, [%4];" \
        : "=r"(r0),"=r"(r1),"=r"(r2),"=r"(r3) : "r"(addr))
#define MMA16816(d, a, b0, b1) \
    asm volatile("mma.sync.aligned.m16n8k16.row.col.f32.f16.f16.f32 " \
        "{%0,%1,%2,%3},{%4,%5,%6,%7},{%8,%9},{%0,%1,%2,%3};" \
        : "+f"((d)[0]),"+f"((d)[1]),"+f"((d)[2]),"+f"((d)[3]) \
        : "r"((a)[0]),"r"((a)[1]),"r"((a)[2]),"r"((a)[3]), "r"(b0),"r"(b1))
#define CPASYNC16(dst, src) \
    asm volatile("cp.async.cg.shared.global [%0], [%1], 16;" :: "r"(dst), "l"(src))
#define CPCOMMIT() asm volatile("cp.async.commit_group;")
#define CPWAIT(n)  asm volatile("cp.async.wait_group %0;" :: "n"(n))

// chunked image element offset within a 128x32 block (64B rows), 16B-chunk XOR swizzle
__device__ __forceinline__ uint32_t swz_elem(int r, int kin) {
    return (uint32_t)(r*32 + ((((kin>>3) ^ ((r>>1)&3)))<<3) + (kin&7));
}
// full image element offset for row m (0..MTOT), channel ch (0..255)
__device__ __forceinline__ size_t img_off(int m, int ch) {
    int tile = m >> 7, mi = m & 127, chunk = ch >> 5, kin = ch & 31;
    return (size_t)(tile*8 + chunk)*4096 + swz_elem(mi, kin);
}

// ---------------- parallel prep: one block per edge set ----------------
__global__ __launch_bounds__(1024) void k_prep(const int* __restrict__ sp, int Esp,
                                               const int* __restrict__ tm, int Etm) {
    __shared__ int   cnt[NN];
    __shared__ float dv [NN];
    __shared__ int   sbuf[2048];
    int set = blockIdx.x;
    const int* edges = (set == 0) ? sp : tm;
    int E = (set == 0) ? Esp : Etm;
    const int* erow = edges;
    const int* ecol = edges + E;
    int t = threadIdx.x;

    for (int i = t; i < NN; i += 1024) cnt[i] = 0;
    __syncthreads();
    for (int e = t; e < E; e += 1024) atomicAdd(&cnt[ecol[e]], 1);
    __syncthreads();
    for (int i = t; i < NN; i += 1024) {
        float d = rsqrtf((float)(cnt[i] + 1));     // +1 self loop
        dv[i] = d; g_dinv[set*NN + i] = d;
    }
    __syncthreads();
    for (int i = t; i < 2048; i += 1024) sbuf[i] = (i < NN) ? cnt[i] : 0;
    __syncthreads();
    for (int off = 1; off < 2048; off <<= 1) {
        int v0 = (t >= off) ? sbuf[t - off] : 0;
        int i1 = t + 1024;
        int v1 = sbuf[i1 - off];
        __syncthreads();
        sbuf[t] += v0; sbuf[i1] += v1;
        __syncthreads();
    }
    int* ptr = g_ptr + set*(NN+1);
    for (int i = t; i <= NN; i += 1024) ptr[i] = (i == 0) ? 0 : sbuf[i-1];
    __syncthreads();
    for (int i = t; i < NN; i += 1024) cnt[i] = 0;   // reuse as cursors
    __syncthreads();
    for (int e = t; e < E; e += 1024) {
        int r = erow[e], c = ecol[e];
        float nrm = dv[r] * dv[c];
        int pos = ptr[c] + atomicAdd(&cnt[c], 1);
        g_esrc [set*MAXE + pos] = r;
        g_enorm[set*MAXE + pos] = nrm;
    }
}

// ---------------- pack/unpack helpers ----------------
__device__ __forceinline__ uint4 pack8h(const float* v) {
    __half2 p0 = __floats2half2_rn(v[0], v[1]);
    __half2 p1 = __floats2half2_rn(v[2], v[3]);
    __half2 p2 = __floats2half2_rn(v[4], v[5]);
    __half2 p3 = __floats2half2_rn(v[6], v[7]);
    uint4 r;
    r.x = *(uint32_t*)&p0; r.y = *(uint32_t*)&p1;
    r.z = *(uint32_t*)&p2; r.w = *(uint32_t*)&p3;
    return r;
}
__device__ __forceinline__ void unpack8h(uint4 p, float* v) {
    float2 f0 = __half22float2(*(__half2*)&p.x);
    float2 f1 = __half22float2(*(__half2*)&p.y);
    float2 f2 = __half22float2(*(__half2*)&p.z);
    float2 f3 = __half22float2(*(__half2*)&p.w);
    v[0]=f0.x; v[1]=f0.y; v[2]=f1.x; v[3]=f1.y;
    v[4]=f2.x; v[5]=f2.y; v[6]=f3.x; v[7]=f3.y;
}

// fused conversion: blocks [0, 13600) convert X; blocks [13600, 13792) convert W1/W2/W3
#define CONVA_BLOCKS (MTOT/8)      // 13600 (8 rows per 256-thr block)
__global__ __launch_bounds__(256) void k_conv(const float* __restrict__ X,
                                              const float* __restrict__ W1,
                                              const float* __restrict__ W2,
                                              const float* __restrict__ W3) {
    if (blockIdx.x < CONVA_BLOCKS) {
        int idx = blockIdx.x * 256 + threadIdx.x;
        int m = idx >> 5, lane = idx & 31;
        int ch = lane * 8;
        float v[8];
        *(float4*)&v[0] = *(const float4*)&X[(size_t)m * CC + ch];
        *(float4*)&v[4] = *(const float4*)&X[(size_t)m * CC + ch + 4];
        *(uint4*)(g_ax + img_off(m, ch)) = pack8h(v);
    } else {
        int wb = blockIdx.x - CONVA_BLOCKS;        // 0..191
        int layer = wb >> 6;
        const float* W = (layer == 0) ? W1 : ((layer == 1) ? W2 : W3);
        int idx = (wb & 63) * 256 + threadIdx.x;
        int n = idx >> 6, kq = idx & 63;
        int k = kq * 4;
        __half2 pA = __floats2half2_rn(W[(size_t)(k+0)*CC + n], W[(size_t)(k+1)*CC + n]);
        __half2 pB = __floats2half2_rn(W[(size_t)(k+2)*CC + n], W[(size_t)(k+3)*CC + n]);
        uint2 pk; pk.x = *(uint32_t*)&pA; pk.y = *(uint32_t*)&pB;
        int nh = n >> 7, ni = n & 127, chunk = k >> 5, kin = k & 31;
        size_t eo = (size_t)layer*65536 + (size_t)(nh*8 + chunk)*4096 + swz_elem(ni, kin);
        *(uint2*)(g_bh + eo) = pk;
    }
}

// ---------------- persistent HMMA GEMM (2 CTAs/SM, B-resident): Him = Aimg @ W ----------------
// grid (296): CTA bid handles half-tiles bid, bid+296, ... (nh = bid&1 fixed).
// B for this nh (64KB) loaded ONCE into smem; only A streams (4 stages x 8KB).
// 256 thr = 8 warps (4m x 2n), warp tile 32x64. smem: B 64KB @0, A stages @65536.
#define ASTAGE 8192
#define GSM (65536 + 4*ASTAGE)
__global__ __launch_bounds__(256, 2) void k_gemm_mma(const __half* __restrict__ Aimg,
                                                     const __half* __restrict__ Bimg,
                                                     __half* __restrict__ Him) {
    extern __shared__ __align__(128) char smc[];
    uint32_t sb = smem_u32(smc);
    int tid = threadIdx.x, wid = tid >> 5, lane = tid & 31;
    int bid = blockIdx.x;
    int nh = bid & 1;
    int mwarp = (wid >> 1) * 32, nwarp = (wid & 1) * 64;

    int nht = (NHT - bid + NSM2 - 1) / NSM2;
    int total = nht * 8;

    const char* gA = (const char*)Aimg;
    const char* gB = (const char*)Bimg + (size_t)nh * 8 * 8192;

    // prologue: load full B half (64KB) into smem (group 0)
    {
        uint32_t off = (uint32_t)tid * 16;
        #pragma unroll
        for (int c = 0; c < 8; c++) {
            CPASYNC16(sb + c*8192 + off,        gB + (size_t)c*8192 + off);
            CPASYNC16(sb + c*8192 + off + 4096, gB + (size_t)c*8192 + off + 4096);
        }
        CPCOMMIT();
    }

    int r15 = lane & 15, hi2 = lane >> 4;
    uint32_t aoff[2]; int asw[2];
    #pragma unroll
    for (int i = 0; i < 2; i++) {
        int mr = mwarp + i*16 + r15;
        aoff[i] = mr * 64; asw[i] = (mr >> 1) & 3;
    }
    uint32_t boff[4]; int bsw[4];
    #pragma unroll
    for (int j = 0; j < 4; j++) {
        int nr = nwarp + j*16 + r15;
        boff[j] = nr * 64; bsw[j] = (nr >> 1) & 3;
    }

    float d[2][8][4];
    #pragma unroll
    for (int i = 0; i < 2; i++)
        #pragma unroll
        for (int j = 0; j < 8; j++)
            #pragma unroll
            for (int q = 0; q < 4; q++) d[i][j][q] = 0.f;

    // issue A chunk g: ht = bid + (g>>3)*296, chunk c = g&7, buffer g&3
    #define ISSUEG(g) do { \
        int _c = (g) & 7; \
        int _tile = (bid + (((g) >> 3) * NSM2)) >> 1; \
        size_t _ab = (size_t)_tile * 65536 + (size_t)_c * 8192; \
        uint32_t so = sb + 65536 + (uint32_t)((g) & 3) * ASTAGE; \
        uint32_t off = (uint32_t)tid * 16; \
        CPASYNC16(so + off,        gA + _ab + off); \
        CPASYNC16(so + off + 4096, gA + _ab + off + 4096); \
        CPCOMMIT(); \
    } while (0)

    ISSUEG(0);
    if (total > 1) ISSUEG(1);
    if (total > 2) ISSUEG(2);
    for (int g = 0; g < total; g++) {
        int rem = total - g - 1;
        if (rem >= 2)      { CPWAIT(2); }
        else if (rem == 1) { CPWAIT(1); }
        else               { CPWAIT(0); }
        __syncthreads();
        int c = g & 7;
        uint32_t abase = sb + 65536 + (uint32_t)(g & 3) * ASTAGE;
        uint32_t bbase = sb + (uint32_t)c * 8192;
        #pragma unroll
        for (int s = 0; s < 2; s++) {
            uint32_t ah[2][4];
            #pragma unroll
            for (int i = 0; i < 2; i++) {
                uint32_t kc = (uint32_t)((((s<<1)|hi2) ^ asw[i]) << 4);
                LDSM4(ah[i][0],ah[i][1],ah[i][2],ah[i][3], abase + aoff[i] + kc);
            }
            #pragma unroll
            for (int jp = 0; jp < 2; jp++) {
                uint32_t bf[2][4];
                #pragma unroll
                for (int q = 0; q < 2; q++) {
                    int j = jp*2 + q;
                    uint32_t kc = (uint32_t)((((s<<1)|hi2) ^ bsw[j]) << 4);
                    LDSM4(bf[q][0],bf[q][1],bf[q][2],bf[q][3], bbase + boff[j] + kc);
                }
                #pragma unroll
                for (int q = 0; q < 2; q++)
                    #pragma unroll
                    for (int i = 0; i < 2; i++) {
                        MMA16816(d[i][4*jp+2*q],   ah[i], bf[q][0], bf[q][2]);
                        MMA16816(d[i][4*jp+2*q+1], ah[i], bf[q][1], bf[q][3]);
                    }
            }
        }
        if (g + 3 < total) ISSUEG(g+3);
        if (c == 7) {
            // epilogue for finished half-tile (overlaps other CTA + in-flight loads)
            int tile = (bid + ((g >> 3) * NSM2)) >> 1;
            int rr = lane >> 2, cp = (lane & 3) * 2;
            size_t tbase = (size_t)tile * 8 * 4096;
            #pragma unroll
            for (int i = 0; i < 2; i++) {
                int mr = mwarp + i*16 + rr;
                #pragma unroll
                for (int j = 0; j < 8; j++) {
                    int col = nh*128 + nwarp + j*8 + cp;
                    int chunk = col >> 5, kin = col & 31;
                    __half2 v01 = __floats2half2_rn(d[i][j][0], d[i][j][1]);
                    __half2 v23 = __floats2half2_rn(d[i][j][2], d[i][j][3]);
                    *(__half2*)(Him + tbase + (size_t)chunk*4096 + swz_elem(mr,   kin)) = v01;
                    *(__half2*)(Him + tbase + (size_t)chunk*4096 + swz_elem(mr+8, kin)) = v23;
                }
            }
            #pragma unroll
            for (int i = 0; i < 2; i++)
                #pragma unroll
                for (int j = 0; j < 8; j++)
                    #pragma unroll
                    for (int q = 0; q < 4; q++) d[i][j][q] = 0.f;
        }
    }
}

// ---------------- aggregation (image-layout fp16 in, fp16 image or fp32 out) ----------------
// acc = sum_in-edges norm*h[b,src,:] + dinv^2*h[b,n,:] + bias (+res), relu.
// 32-lane groups (8 ch/lane), 8 batches per block; 4-edge unroll, gathers batched for MLP.
__global__ __launch_bounds__(256) void k_agg(const __half* __restrict__ Him, int set,
                                             const float* __restrict__ bias,
                                             const float* __restrict__ residual,
                                             float* __restrict__ out,
                                             __half* __restrict__ Aimg) {
    int g    = threadIdx.x >> 5;           // batch sub-group 0..7
    int lane = threadIdx.x & 31;           // channel/8
    int n = blockIdx.x;
    int b = blockIdx.y * 8 + g;
    int ch = lane * 8;

    const int* ptr = g_ptr + set*(NN+1);
    int p0 = __ldg(&ptr[n]), p1 = __ldg(&ptr[n+1]);
    float dn = __ldg(&g_dinv[set*NN + n]);
    int bbase = b * NN;
    int m = bbase + n;

    float v[8], acc[8];
    unpack8h(*(const uint4*)(Him + img_off(m, ch)), v);
    float w = dn * dn;
    #pragma unroll
    for (int e = 0; e < 8; e++) acc[e] = w * v[e];

    int off = set*MAXE;
    int j = p0;
    for (; j + 4 <= p1; j += 4) {
        int   s0 = __ldg(&g_esrc [off + j]);
        int   s1 = __ldg(&g_esrc [off + j + 1]);
        int   s2 = __ldg(&g_esrc [off + j + 2]);
        int   s3 = __ldg(&g_esrc [off + j + 3]);
        float w0 = __ldg(&g_enorm[off + j]);
        float w1 = __ldg(&g_enorm[off + j + 1]);
        float w2 = __ldg(&g_enorm[off + j + 2]);
        float w3 = __ldg(&g_enorm[off + j + 3]);
        uint4 pk0 = *(const uint4*)(Him + img_off(bbase + s0, ch));
        uint4 pk1 = *(const uint4*)(Him + img_off(bbase + s1, ch));
        uint4 pk2 = *(const uint4*)(Him + img_off(bbase + s2, ch));
        uint4 pk3 = *(const uint4*)(Him + img_off(bbase + s3, ch));
        float u0[8], u1[8], u2[8], u3[8];
        unpack8h(pk0, u0); unpack8h(pk1, u1);
        unpack8h(pk2, u2); unpack8h(pk3, u3);
        #pragma unroll
        for (int e = 0; e < 8; e++)
            acc[e] += w0*u0[e] + w1*u1[e] + w2*u2[e] + w3*u3[e];
    }
    if (j + 2 <= p1) {
        int   s0 = __ldg(&g_esrc [off + j]);
        int   s1 = __ldg(&g_esrc [off + j + 1]);
        float w0 = __ldg(&g_enorm[off + j]);
        float w1 = __ldg(&g_enorm[off + j + 1]);
        uint4 pk0 = *(const uint4*)(Him + img_off(bbase + s0, ch));
        uint4 pk1 = *(const uint4*)(Him + img_off(bbase + s1, ch));
        float u0[8], u1[8];
        unpack8h(pk0, u0); unpack8h(pk1, u1);
        #pragma unroll
        for (int e = 0; e < 8; e++) acc[e] += w0*u0[e] + w1*u1[e];
        j += 2;
    }
    if (j < p1) {
        int   s0 = __ldg(&g_esrc [off + j]);
        float w0 = __ldg(&g_enorm[off + j]);
        float u0[8];
        unpack8h(*(const uint4*)(Him + img_off(bbase + s0, ch)), u0);
        #pragma unroll
        for (int e = 0; e < 8; e++) acc[e] += w0*u0[e];
    }

    float4 bi0 = *(const float4*)&bias[ch];
    float4 bi1 = *(const float4*)&bias[ch + 4];
    acc[0]+=bi0.x; acc[1]+=bi0.y; acc[2]+=bi0.z; acc[3]+=bi0.w;
    acc[4]+=bi1.x; acc[5]+=bi1.y; acc[6]+=bi1.z; acc[7]+=bi1.w;
    if (residual) {
        size_t rb = (size_t)m * CC + ch;
        float4 r0 = *(const float4*)&residual[rb];
        float4 r1 = *(const float4*)&residual[rb + 4];
        acc[0]+=r0.x; acc[1]+=r0.y; acc[2]+=r0.z; acc[3]+=r0.w;
        acc[4]+=r1.x; acc[5]+=r1.y; acc[6]+=r1.z; acc[7]+=r1.w;
    }
    #pragma unroll
    for (int e = 0; e < 8; e++) acc[e] = fmaxf(acc[e], 0.f);

    if (Aimg) {
        *(uint4*)(Aimg + img_off(m, ch)) = pack8h(acc);
    } else {
        size_t ob = (size_t)m * CC + ch;
        *(float4*)&out[ob]     = make_float4(acc[0], acc[1], acc[2], acc[3]);
        *(float4*)&out[ob + 4] = make_float4(acc[4], acc[5], acc[6], acc[7]);
    }
}

// ---------------- launch ----------------
extern "C" void kernel_launch(void* const* d_in, const int* in_sizes, int n_in,
                              void* d_out, int out_size) {
    const float* x  = (const float*)d_in[0];
    const float* W1 = (const float*)d_in[1];
    const float* b1 = (const float*)d_in[2];
    const float* W2 = (const float*)d_in[3];
    const float* b2 = (const float*)d_in[4];
    const float* W3 = (const float*)d_in[5];
    const float* b3 = (const float*)d_in[6];
    const int*   sp = (const int*)d_in[7];
    const int*   tm = (const int*)d_in[8];
    int Esp = in_sizes[7] / 2;
    int Etm = in_sizes[8] / 2;
    float* out = (float*)d_out;

    __half *ax, *hx, *bh;
    cudaGetSymbolAddress((void**)&ax, g_ax);
    cudaGetSymbolAddress((void**)&hx, g_hx);
    cudaGetSymbolAddress((void**)&bh, g_bh);

    cudaFuncSetAttribute(k_gemm_mma, cudaFuncAttributeMaxDynamicSharedMemorySize, GSM);

    dim3 ga(NN, BB/8);                // (1700, 8)

    // launches: conv(1), prep(2), gemm1(3), agg1(4) — slot 4 profiled => k_agg
    k_conv<<<CONVA_BLOCKS + 192, 256>>>(x, W1, W2, W3);
    k_prep<<<2, 1024>>>(sp, Esp, tm, Etm);

    // conv1
    k_gemm_mma<<<NSM2, 256, GSM>>>(ax, bh, hx);
    k_agg<<<ga, 256>>>(hx, 0, b1, nullptr, nullptr, ax);   // launch #4 — profiled
    // conv2
    k_gemm_mma<<<NSM2, 256, GSM>>>(ax, bh + 65536, hx);
    k_agg<<<ga, 256>>>(hx, 1, b2, nullptr, nullptr, ax);
    // conv3
    k_gemm_mma<<<NSM2, 256, GSM>>>(ax, bh + 2*65536, hx);
    k_agg<<<ga, 256>>>(hx, 0, b3, x, out, nullptr);
}

// round 15
// speedup vs baseline: 3.5502x; 1.0548x over previous
#include <cuda_runtime.h>
#include <cuda_fp16.h>
#include <cstdint>

typedef unsigned long long ull;

#define BB 64
#define NN 1700
#define CC 256
#define MAXE 16384
#define MTOT (BB*NN)
#define MTILES (MTOT/128)          // 850
#define NHT (MTILES*2)             // 1700 half-tiles (128x128)
#define NSM2 296                   // 2 CTAs per SM

// ---------------- scratch (device globals; no allocation allowed) ----------------
__device__ __half g_ax[(size_t)MTOT*CC];           // A input images (fp16, chunked+swizzled, GEMM input)
__device__ __half g_hx[(size_t)MTOT*CC];           // H output (fp16, PLAIN row-major, agg input)
__device__ __half g_bh[3*65536];                   // B fp16 images per layer
__device__ int   g_ptr[2*(NN+1)];
__device__ float g_dinv[2*NN];
__device__ int   g_esrc[2*MAXE];
__device__ float g_enorm[2*MAXE];

// ---------------- PTX helpers (all sm_80-class: valid for compute_103) ----------------
__device__ __forceinline__ uint32_t smem_u32(const void* p) {
    uint32_t a;
    asm("{ .reg .u64 t; cvta.to.shared.u64 t, %1; cvt.u32.u64 %0, t; }" : "=r"(a) : "l"(p));
    return a;
}
#define LDSM4(r0,r1,r2,r3,addr) \
    asm volatile("ldmatrix.sync.aligned.m8n8.x4.shared.b16 {%0,%1,%2,%3}, [%4];" \
        : "=r"(r0),"=r"(r1),"=r"(r2),"=r"(r3) : "r"(addr))
#define MMA16816(d, a, b0, b1) \
    asm volatile("mma.sync.aligned.m16n8k16.row.col.f32.f16.f16.f32 " \
        "{%0,%1,%2,%3},{%4,%5,%6,%7},{%8,%9},{%0,%1,%2,%3};" \
        : "+f"((d)[0]),"+f"((d)[1]),"+f"((d)[2]),"+f"((d)[3]) \
        : "r"((a)[0]),"r"((a)[1]),"r"((a)[2]),"r"((a)[3]), "r"(b0),"r"(b1))
#define CPASYNC16(dst, src) \
    asm volatile("cp.async.cg.shared.global [%0], [%1], 16;" :: "r"(dst), "l"(src))
#define CPCOMMIT() asm volatile("cp.async.commit_group;")
#define CPWAIT(n)  asm volatile("cp.async.wait_group %0;" :: "n"(n))

// chunked image element offset within a 128x32 block (64B rows), 16B-chunk XOR swizzle
__device__ __forceinline__ uint32_t swz_elem(int r, int kin) {
    return (uint32_t)(r*32 + ((((kin>>3) ^ ((r>>1)&3)))<<3) + (kin&7));
}
// full image element offset for row m (0..MTOT), channel ch (0..255)
__device__ __forceinline__ size_t img_off(int m, int ch) {
    int tile = m >> 7, mi = m & 127, chunk = ch >> 5, kin = ch & 31;
    return (size_t)(tile*8 + chunk)*4096 + swz_elem(mi, kin);
}

// ---------------- parallel prep: one block per edge set ----------------
__global__ __launch_bounds__(1024) void k_prep(const int* __restrict__ sp, int Esp,
                                               const int* __restrict__ tm, int Etm) {
    __shared__ int   cnt[NN];
    __shared__ float dv [NN];
    __shared__ int   sbuf[2048];
    int set = blockIdx.x;
    const int* edges = (set == 0) ? sp : tm;
    int E = (set == 0) ? Esp : Etm;
    const int* erow = edges;
    const int* ecol = edges + E;
    int t = threadIdx.x;

    for (int i = t; i < NN; i += 1024) cnt[i] = 0;
    __syncthreads();
    for (int e = t; e < E; e += 1024) atomicAdd(&cnt[ecol[e]], 1);
    __syncthreads();
    for (int i = t; i < NN; i += 1024) {
        float d = rsqrtf((float)(cnt[i] + 1));     // +1 self loop
        dv[i] = d; g_dinv[set*NN + i] = d;
    }
    __syncthreads();
    for (int i = t; i < 2048; i += 1024) sbuf[i] = (i < NN) ? cnt[i] : 0;
    __syncthreads();
    for (int off = 1; off < 2048; off <<= 1) {
        int v0 = (t >= off) ? sbuf[t - off] : 0;
        int i1 = t + 1024;
        int v1 = sbuf[i1 - off];
        __syncthreads();
        sbuf[t] += v0; sbuf[i1] += v1;
        __syncthreads();
    }
    int* ptr = g_ptr + set*(NN+1);
    for (int i = t; i <= NN; i += 1024) ptr[i] = (i == 0) ? 0 : sbuf[i-1];
    __syncthreads();
    for (int i = t; i < NN; i += 1024) cnt[i] = 0;   // reuse as cursors
    __syncthreads();
    for (int e = t; e < E; e += 1024) {
        int r = erow[e], c = ecol[e];
        float nrm = dv[r] * dv[c];
        int pos = ptr[c] + atomicAdd(&cnt[c], 1);
        g_esrc [set*MAXE + pos] = r;
        g_enorm[set*MAXE + pos] = nrm;
    }
}

// ---------------- pack/unpack helpers ----------------
__device__ __forceinline__ uint4 pack8h(const float* v) {
    __half2 p0 = __floats2half2_rn(v[0], v[1]);
    __half2 p1 = __floats2half2_rn(v[2], v[3]);
    __half2 p2 = __floats2half2_rn(v[4], v[5]);
    __half2 p3 = __floats2half2_rn(v[6], v[7]);
    uint4 r;
    r.x = *(uint32_t*)&p0; r.y = *(uint32_t*)&p1;
    r.z = *(uint32_t*)&p2; r.w = *(uint32_t*)&p3;
    return r;
}
__device__ __forceinline__ void unpack8h(uint4 p, float* v) {
    float2 f0 = __half22float2(*(__half2*)&p.x);
    float2 f1 = __half22float2(*(__half2*)&p.y);
    float2 f2 = __half22float2(*(__half2*)&p.z);
    float2 f3 = __half22float2(*(__half2*)&p.w);
    v[0]=f0.x; v[1]=f0.y; v[2]=f1.x; v[3]=f1.y;
    v[4]=f2.x; v[5]=f2.y; v[6]=f3.x; v[7]=f3.y;
}

// fused conversion: blocks [0, 13600) convert X; blocks [13600, 13792) convert W1/W2/W3
#define CONVA_BLOCKS (MTOT/8)      // 13600 (8 rows per 256-thr block)
__global__ __launch_bounds__(256) void k_conv(const float* __restrict__ X,
                                              const float* __restrict__ W1,
                                              const float* __restrict__ W2,
                                              const float* __restrict__ W3) {
    if (blockIdx.x < CONVA_BLOCKS) {
        int idx = blockIdx.x * 256 + threadIdx.x;
        int m = idx >> 5, lane = idx & 31;
        int ch = lane * 8;
        float v[8];
        *(float4*)&v[0] = *(const float4*)&X[(size_t)m * CC + ch];
        *(float4*)&v[4] = *(const float4*)&X[(size_t)m * CC + ch + 4];
        *(uint4*)(g_ax + img_off(m, ch)) = pack8h(v);
    } else {
        int wb = blockIdx.x - CONVA_BLOCKS;        // 0..191
        int layer = wb >> 6;
        const float* W = (layer == 0) ? W1 : ((layer == 1) ? W2 : W3);
        int idx = (wb & 63) * 256 + threadIdx.x;
        int n = idx >> 6, kq = idx & 63;
        int k = kq * 4;
        __half2 pA = __floats2half2_rn(W[(size_t)(k+0)*CC + n], W[(size_t)(k+1)*CC + n]);
        __half2 pB = __floats2half2_rn(W[(size_t)(k+2)*CC + n], W[(size_t)(k+3)*CC + n]);
        uint2 pk; pk.x = *(uint32_t*)&pA; pk.y = *(uint32_t*)&pB;
        int nh = n >> 7, ni = n & 127, chunk = k >> 5, kin = k & 31;
        size_t eo = (size_t)layer*65536 + (size_t)(nh*8 + chunk)*4096 + swz_elem(ni, kin);
        *(uint2*)(g_bh + eo) = pk;
    }
}

// ---------------- persistent HMMA GEMM (2 CTAs/SM, B-resident): Hplain = Aimg @ W ----------------
// grid (296): CTA bid handles half-tiles bid, bid+296, ... (nh = bid&1 fixed).
// B for this nh (64KB) loaded ONCE into smem; only A streams (4 stages x 8KB).
// 256 thr = 8 warps (4m x 2n), warp tile 32x64. smem: B 64KB @0, A stages @65536.
// Output written as fp16 PLAIN row-major [m][ch].
#define ASTAGE 8192
#define GSM (65536 + 4*ASTAGE)
__global__ __launch_bounds__(256, 2) void k_gemm_mma(const __half* __restrict__ Aimg,
                                                     const __half* __restrict__ Bimg,
                                                     __half* __restrict__ Hp) {
    extern __shared__ __align__(128) char smc[];
    uint32_t sb = smem_u32(smc);
    int tid = threadIdx.x, wid = tid >> 5, lane = tid & 31;
    int bid = blockIdx.x;
    int nh = bid & 1;
    int mwarp = (wid >> 1) * 32, nwarp = (wid & 1) * 64;

    int nht = (NHT - bid + NSM2 - 1) / NSM2;
    int total = nht * 8;

    const char* gA = (const char*)Aimg;
    const char* gB = (const char*)Bimg + (size_t)nh * 8 * 8192;

    // prologue: load full B half (64KB) into smem (group 0)
    {
        uint32_t off = (uint32_t)tid * 16;
        #pragma unroll
        for (int c = 0; c < 8; c++) {
            CPASYNC16(sb + c*8192 + off,        gB + (size_t)c*8192 + off);
            CPASYNC16(sb + c*8192 + off + 4096, gB + (size_t)c*8192 + off + 4096);
        }
        CPCOMMIT();
    }

    int r15 = lane & 15, hi2 = lane >> 4;
    uint32_t aoff[2]; int asw[2];
    #pragma unroll
    for (int i = 0; i < 2; i++) {
        int mr = mwarp + i*16 + r15;
        aoff[i] = mr * 64; asw[i] = (mr >> 1) & 3;
    }
    uint32_t boff[4]; int bsw[4];
    #pragma unroll
    for (int j = 0; j < 4; j++) {
        int nr = nwarp + j*16 + r15;
        boff[j] = nr * 64; bsw[j] = (nr >> 1) & 3;
    }

    float d[2][8][4];
    #pragma unroll
    for (int i = 0; i < 2; i++)
        #pragma unroll
        for (int j = 0; j < 8; j++)
            #pragma unroll
            for (int q = 0; q < 4; q++) d[i][j][q] = 0.f;

    // issue A chunk g: ht = bid + (g>>3)*296, chunk c = g&7, buffer g&3
    #define ISSUEG(g) do { \
        int _c = (g) & 7; \
        int _tile = (bid + (((g) >> 3) * NSM2)) >> 1; \
        size_t _ab = (size_t)_tile * 65536 + (size_t)_c * 8192; \
        uint32_t so = sb + 65536 + (uint32_t)((g) & 3) * ASTAGE; \
        uint32_t off = (uint32_t)tid * 16; \
        CPASYNC16(so + off,        gA + _ab + off); \
        CPASYNC16(so + off + 4096, gA + _ab + off + 4096); \
        CPCOMMIT(); \
    } while (0)

    ISSUEG(0);
    if (total > 1) ISSUEG(1);
    if (total > 2) ISSUEG(2);
    for (int g = 0; g < total; g++) {
        int rem = total - g - 1;
        if (rem >= 2)      { CPWAIT(2); }
        else if (rem == 1) { CPWAIT(1); }
        else               { CPWAIT(0); }
        __syncthreads();
        int c = g & 7;
        uint32_t abase = sb + 65536 + (uint32_t)(g & 3) * ASTAGE;
        uint32_t bbase = sb + (uint32_t)c * 8192;
        #pragma unroll
        for (int s = 0; s < 2; s++) {
            uint32_t ah[2][4];
            #pragma unroll
            for (int i = 0; i < 2; i++) {
                uint32_t kc = (uint32_t)((((s<<1)|hi2) ^ asw[i]) << 4);
                LDSM4(ah[i][0],ah[i][1],ah[i][2],ah[i][3], abase + aoff[i] + kc);
            }
            #pragma unroll
            for (int jp = 0; jp < 2; jp++) {
                uint32_t bf[2][4];
                #pragma unroll
                for (int q = 0; q < 2; q++) {
                    int j = jp*2 + q;
                    uint32_t kc = (uint32_t)((((s<<1)|hi2) ^ bsw[j]) << 4);
                    LDSM4(bf[q][0],bf[q][1],bf[q][2],bf[q][3], bbase + boff[j] + kc);
                }
                #pragma unroll
                for (int q = 0; q < 2; q++)
                    #pragma unroll
                    for (int i = 0; i < 2; i++) {
                        MMA16816(d[i][4*jp+2*q],   ah[i], bf[q][0], bf[q][2]);
                        MMA16816(d[i][4*jp+2*q+1], ah[i], bf[q][1], bf[q][3]);
                    }
            }
        }
        if (g + 3 < total) ISSUEG(g+3);
        if (c == 7) {
            // epilogue: write plain row-major fp16 (overlaps in-flight loads)
            int tile = (bid + ((g >> 3) * NSM2)) >> 1;
            int rr = lane >> 2, cp = (lane & 3) * 2;
            #pragma unroll
            for (int i = 0; i < 2; i++) {
                size_t row = (size_t)tile*128 + mwarp + i*16 + rr;
                #pragma unroll
                for (int j = 0; j < 8; j++) {
                    int col = nh*128 + nwarp + j*8 + cp;
                    __half2 v01 = __floats2half2_rn(d[i][j][0], d[i][j][1]);
                    __half2 v23 = __floats2half2_rn(d[i][j][2], d[i][j][3]);
                    *(__half2*)(Hp + row*CC + col)       = v01;
                    *(__half2*)(Hp + (row+8)*CC + col)   = v23;
                }
            }
            #pragma unroll
            for (int i = 0; i < 2; i++)
                #pragma unroll
                for (int j = 0; j < 8; j++)
                    #pragma unroll
                    for (int q = 0; q < 4; q++) d[i][j][q] = 0.f;
        }
    }
}

// ---------------- aggregation (plain fp16 in; fp16 image or fp32 out) ----------------
// acc = sum_in-edges norm*h[b,src,:] + dinv^2*h[b,n,:] + bias (+res), relu.
// 32-lane groups (8 ch/lane), 8 batches per block; 4-edge unroll, contiguous 512B warp gathers.
__global__ __launch_bounds__(256) void k_agg(const __half* __restrict__ Hp, int set,
                                             const float* __restrict__ bias,
                                             const float* __restrict__ residual,
                                             float* __restrict__ out,
                                             __half* __restrict__ Aimg) {
    int g    = threadIdx.x >> 5;           // batch sub-group 0..7
    int lane = threadIdx.x & 31;           // channel/8
    int n = blockIdx.x;
    int b = blockIdx.y * 8 + g;
    int ch = lane * 8;

    const int* ptr = g_ptr + set*(NN+1);
    int p0 = __ldg(&ptr[n]), p1 = __ldg(&ptr[n+1]);
    float dn = __ldg(&g_dinv[set*NN + n]);
    int bbase = b * NN;
    int m = bbase + n;
    const __half* Hb = Hp + (size_t)bbase * CC + ch;

    float v[8], acc[8];
    unpack8h(*(const uint4*)(Hp + (size_t)m * CC + ch), v);
    float w = dn * dn;
    #pragma unroll
    for (int e = 0; e < 8; e++) acc[e] = w * v[e];

    int off = set*MAXE;
    int j = p0;
    for (; j + 4 <= p1; j += 4) {
        int   s0 = __ldg(&g_esrc [off + j]);
        int   s1 = __ldg(&g_esrc [off + j + 1]);
        int   s2 = __ldg(&g_esrc [off + j + 2]);
        int   s3 = __ldg(&g_esrc [off + j + 3]);
        float w0 = __ldg(&g_enorm[off + j]);
        float w1 = __ldg(&g_enorm[off + j + 1]);
        float w2 = __ldg(&g_enorm[off + j + 2]);
        float w3 = __ldg(&g_enorm[off + j + 3]);
        uint4 pk0 = *(const uint4*)(Hb + (size_t)s0 * CC);
        uint4 pk1 = *(const uint4*)(Hb + (size_t)s1 * CC);
        uint4 pk2 = *(const uint4*)(Hb + (size_t)s2 * CC);
        uint4 pk3 = *(const uint4*)(Hb + (size_t)s3 * CC);
        float u0[8], u1[8], u2[8], u3[8];
        unpack8h(pk0, u0); unpack8h(pk1, u1);
        unpack8h(pk2, u2); unpack8h(pk3, u3);
        #pragma unroll
        for (int e = 0; e < 8; e++)
            acc[e] += w0*u0[e] + w1*u1[e] + w2*u2[e] + w3*u3[e];
    }
    if (j + 2 <= p1) {
        int   s0 = __ldg(&g_esrc [off + j]);
        int   s1 = __ldg(&g_esrc [off + j + 1]);
        float w0 = __ldg(&g_enorm[off + j]);
        float w1 = __ldg(&g_enorm[off + j + 1]);
        uint4 pk0 = *(const uint4*)(Hb + (size_t)s0 * CC);
        uint4 pk1 = *(const uint4*)(Hb + (size_t)s1 * CC);
        float u0[8], u1[8];
        unpack8h(pk0, u0); unpack8h(pk1, u1);
        #pragma unroll
        for (int e = 0; e < 8; e++) acc[e] += w0*u0[e] + w1*u1[e];
        j += 2;
    }
    if (j < p1) {
        int   s0 = __ldg(&g_esrc [off + j]);
        float w0 = __ldg(&g_enorm[off + j]);
        float u0[8];
        unpack8h(*(const uint4*)(Hb + (size_t)s0 * CC), u0);
        #pragma unroll
        for (int e = 0; e < 8; e++) acc[e] += w0*u0[e];
    }

    float4 bi0 = *(const float4*)&bias[ch];
    float4 bi1 = *(const float4*)&bias[ch + 4];
    acc[0]+=bi0.x; acc[1]+=bi0.y; acc[2]+=bi0.z; acc[3]+=bi0.w;
    acc[4]+=bi1.x; acc[5]+=bi1.y; acc[6]+=bi1.z; acc[7]+=bi1.w;
    if (residual) {
        size_t rb = (size_t)m * CC + ch;
        float4 r0 = *(const float4*)&residual[rb];
        float4 r1 = *(const float4*)&residual[rb + 4];
        acc[0]+=r0.x; acc[1]+=r0.y; acc[2]+=r0.z; acc[3]+=r0.w;
        acc[4]+=r1.x; acc[5]+=r1.y; acc[6]+=r1.z; acc[7]+=r1.w;
    }
    #pragma unroll
    for (int e = 0; e < 8; e++) acc[e] = fmaxf(acc[e], 0.f);

    if (Aimg) {
        *(uint4*)(Aimg + img_off(m, ch)) = pack8h(acc);
    } else {
        size_t ob = (size_t)m * CC + ch;
        *(float4*)&out[ob]     = make_float4(acc[0], acc[1], acc[2], acc[3]);
        *(float4*)&out[ob + 4] = make_float4(acc[4], acc[5], acc[6], acc[7]);
    }
}

// ---------------- launch ----------------
extern "C" void kernel_launch(void* const* d_in, const int* in_sizes, int n_in,
                              void* d_out, int out_size) {
    const float* x  = (const float*)d_in[0];
    const float* W1 = (const float*)d_in[1];
    const float* b1 = (const float*)d_in[2];
    const float* W2 = (const float*)d_in[3];
    const float* b2 = (const float*)d_in[4];
    const float* W3 = (const float*)d_in[5];
    const float* b3 = (const float*)d_in[6];
    const int*   sp = (const int*)d_in[7];
    const int*   tm = (const int*)d_in[8];
    int Esp = in_sizes[7] / 2;
    int Etm = in_sizes[8] / 2;
    float* out = (float*)d_out;

    __half *ax, *hx, *bh;
    cudaGetSymbolAddress((void**)&ax, g_ax);
    cudaGetSymbolAddress((void**)&hx, g_hx);
    cudaGetSymbolAddress((void**)&bh, g_bh);

    cudaFuncSetAttribute(k_gemm_mma, cudaFuncAttributeMaxDynamicSharedMemorySize, GSM);

    dim3 ga(NN, BB/8);                // (1700, 8)

    // launches: conv(1), prep(2), gemm1(3), agg1(4) — slot 4 profiled => k_agg
    k_conv<<<CONVA_BLOCKS + 192, 256>>>(x, W1, W2, W3);
    k_prep<<<2, 1024>>>(sp, Esp, tm, Etm);

    // conv1
    k_gemm_mma<<<NSM2, 256, GSM>>>(ax, bh, hx);
    k_agg<<<ga, 256>>>(hx, 0, b1, nullptr, nullptr, ax);   // launch #4 — profiled
    // conv2
    k_gemm_mma<<<NSM2, 256, GSM>>>(ax, bh + 65536, hx);
    k_agg<<<ga, 256>>>(hx, 1, b2, nullptr, nullptr, ax);
    // conv3
    k_gemm_mma<<<NSM2, 256, GSM>>>(ax, bh + 2*65536, hx);
    k_agg<<<ga, 256>>>(hx, 0, b3, x, out, nullptr);
}

// round 16
// speedup vs baseline: 3.7768x; 1.0638x over previous
#include <cuda_runtime.h>
#include <cuda_fp16.h>
#include <cstdint>

typedef unsigned long long ull;

#define BB 64
#define NN 1700
#define CC 256
#define MAXE 16384
#define MTOT (BB*NN)
#define MTILES (MTOT/128)          // 850
#define NHT (MTILES*2)             // 1700 half-tiles (128x128)
#define NSM2 296                   // 2 CTAs per SM

// ---------------- scratch (device globals; no allocation allowed) ----------------
__device__ __half g_ax[(size_t)MTOT*CC];           // A input images (fp16, chunked+swizzled, GEMM input)
__device__ __half g_hx[(size_t)MTOT*CC];           // H output (fp16, PLAIN row-major, agg input)
__device__ __half g_bh[3*65536];                   // B fp16 images per layer
__device__ int      g_ptr[2*(NN+1)];
__device__ float    g_dinv[2*NN];
__device__ int      g_esrc[2*MAXE];
__device__ uint32_t g_enorm2[2*MAXE];              // edge norms pre-packed as half2

// ---------------- PTX helpers (all sm_80-class: valid for compute_103) ----------------
__device__ __forceinline__ uint32_t smem_u32(const void* p) {
    uint32_t a;
    asm("{ .reg .u64 t; cvta.to.shared.u64 t, %1; cvt.u32.u64 %0, t; }" : "=r"(a) : "l"(p));
    return a;
}
#define LDSM4(r0,r1,r2,r3,addr) \
    asm volatile("ldmatrix.sync.aligned.m8n8.x4.shared.b16 {%0,%1,%2,%3}, [%4];" \
        : "=r"(r0),"=r"(r1),"=r"(r2),"=r"(r3) : "r"(addr))
#define MMA16816(d, a, b0, b1) \
    asm volatile("mma.sync.aligned.m16n8k16.row.col.f32.f16.f16.f32 " \
        "{%0,%1,%2,%3},{%4,%5,%6,%7},{%8,%9},{%0,%1,%2,%3};" \
        : "+f"((d)[0]),"+f"((d)[1]),"+f"((d)[2]),"+f"((d)[3]) \
        : "r"((a)[0]),"r"((a)[1]),"r"((a)[2]),"r"((a)[3]), "r"(b0),"r"(b1))
#define CPASYNC16(dst, src) \
    asm volatile("cp.async.cg.shared.global [%0], [%1], 16;" :: "r"(dst), "l"(src))
#define CPCOMMIT() asm volatile("cp.async.commit_group;")
#define CPWAIT(n)  asm volatile("cp.async.wait_group %0;" :: "n"(n))

// chunked image element offset within a 128x32 block (64B rows), 16B-chunk XOR swizzle
__device__ __forceinline__ uint32_t swz_elem(int r, int kin) {
    return (uint32_t)(r*32 + ((((kin>>3) ^ ((r>>1)&3)))<<3) + (kin&7));
}
// full image element offset for row m (0..MTOT), channel ch (0..255)
__device__ __forceinline__ size_t img_off(int m, int ch) {
    int tile = m >> 7, mi = m & 127, chunk = ch >> 5, kin = ch & 31;
    return (size_t)(tile*8 + chunk)*4096 + swz_elem(mi, kin);
}

// ---------------- parallel prep: one block per edge set ----------------
__global__ __launch_bounds__(1024) void k_prep(const int* __restrict__ sp, int Esp,
                                               const int* __restrict__ tm, int Etm) {
    __shared__ int   cnt[NN];
    __shared__ float dv [NN];
    __shared__ int   sbuf[2048];
    int set = blockIdx.x;
    const int* edges = (set == 0) ? sp : tm;
    int E = (set == 0) ? Esp : Etm;
    const int* erow = edges;
    const int* ecol = edges + E;
    int t = threadIdx.x;

    for (int i = t; i < NN; i += 1024) cnt[i] = 0;
    __syncthreads();
    for (int e = t; e < E; e += 1024) atomicAdd(&cnt[ecol[e]], 1);
    __syncthreads();
    for (int i = t; i < NN; i += 1024) {
        float d = rsqrtf((float)(cnt[i] + 1));     // +1 self loop
        dv[i] = d; g_dinv[set*NN + i] = d;
    }
    __syncthreads();
    for (int i = t; i < 2048; i += 1024) sbuf[i] = (i < NN) ? cnt[i] : 0;
    __syncthreads();
    for (int off = 1; off < 2048; off <<= 1) {
        int v0 = (t >= off) ? sbuf[t - off] : 0;
        int i1 = t + 1024;
        int v1 = sbuf[i1 - off];
        __syncthreads();
        sbuf[t] += v0; sbuf[i1] += v1;
        __syncthreads();
    }
    int* ptr = g_ptr + set*(NN+1);
    for (int i = t; i <= NN; i += 1024) ptr[i] = (i == 0) ? 0 : sbuf[i-1];
    __syncthreads();
    for (int i = t; i < NN; i += 1024) cnt[i] = 0;   // reuse as cursors
    __syncthreads();
    for (int e = t; e < E; e += 1024) {
        int r = erow[e], c = ecol[e];
        float nrm = dv[r] * dv[c];
        __half2 nh = __float2half2_rn(nrm);
        int pos = ptr[c] + atomicAdd(&cnt[c], 1);
        g_esrc  [set*MAXE + pos] = r;
        g_enorm2[set*MAXE + pos] = *(uint32_t*)&nh;
    }
}

// ---------------- pack/unpack helpers ----------------
__device__ __forceinline__ uint4 pack8h(const float* v) {
    __half2 p0 = __floats2half2_rn(v[0], v[1]);
    __half2 p1 = __floats2half2_rn(v[2], v[3]);
    __half2 p2 = __floats2half2_rn(v[4], v[5]);
    __half2 p3 = __floats2half2_rn(v[6], v[7]);
    uint4 r;
    r.x = *(uint32_t*)&p0; r.y = *(uint32_t*)&p1;
    r.z = *(uint32_t*)&p2; r.w = *(uint32_t*)&p3;
    return r;
}

// fused conversion: blocks [0, 13600) convert X; blocks [13600, 13792) convert W1/W2/W3
#define CONVA_BLOCKS (MTOT/8)      // 13600 (8 rows per 256-thr block)
__global__ __launch_bounds__(256) void k_conv(const float* __restrict__ X,
                                              const float* __restrict__ W1,
                                              const float* __restrict__ W2,
                                              const float* __restrict__ W3) {
    if (blockIdx.x < CONVA_BLOCKS) {
        int idx = blockIdx.x * 256 + threadIdx.x;
        int m = idx >> 5, lane = idx & 31;
        int ch = lane * 8;
        float v[8];
        *(float4*)&v[0] = *(const float4*)&X[(size_t)m * CC + ch];
        *(float4*)&v[4] = *(const float4*)&X[(size_t)m * CC + ch + 4];
        *(uint4*)(g_ax + img_off(m, ch)) = pack8h(v);
    } else {
        int wb = blockIdx.x - CONVA_BLOCKS;        // 0..191
        int layer = wb >> 6;
        const float* W = (layer == 0) ? W1 : ((layer == 1) ? W2 : W3);
        int idx = (wb & 63) * 256 + threadIdx.x;
        int n = idx >> 6, kq = idx & 63;
        int k = kq * 4;
        __half2 pA = __floats2half2_rn(W[(size_t)(k+0)*CC + n], W[(size_t)(k+1)*CC + n]);
        __half2 pB = __floats2half2_rn(W[(size_t)(k+2)*CC + n], W[(size_t)(k+3)*CC + n]);
        uint2 pk; pk.x = *(uint32_t*)&pA; pk.y = *(uint32_t*)&pB;
        int nh = n >> 7, ni = n & 127, chunk = k >> 5, kin = k & 31;
        size_t eo = (size_t)layer*65536 + (size_t)(nh*8 + chunk)*4096 + swz_elem(ni, kin);
        *(uint2*)(g_bh + eo) = pk;
    }
}

// ---------------- persistent HMMA GEMM (2 CTAs/SM, B-resident): Hplain = Aimg @ W ----------------
#define ASTAGE 8192
#define GSM (65536 + 4*ASTAGE)
__global__ __launch_bounds__(256, 2) void k_gemm_mma(const __half* __restrict__ Aimg,
                                                     const __half* __restrict__ Bimg,
                                                     __half* __restrict__ Hp) {
    extern __shared__ __align__(128) char smc[];
    uint32_t sb = smem_u32(smc);
    int tid = threadIdx.x, wid = tid >> 5, lane = tid & 31;
    int bid = blockIdx.x;
    int nh = bid & 1;
    int mwarp = (wid >> 1) * 32, nwarp = (wid & 1) * 64;

    int nht = (NHT - bid + NSM2 - 1) / NSM2;
    int total = nht * 8;

    const char* gA = (const char*)Aimg;
    const char* gB = (const char*)Bimg + (size_t)nh * 8 * 8192;

    // prologue: load full B half (64KB) into smem (group 0)
    {
        uint32_t off = (uint32_t)tid * 16;
        #pragma unroll
        for (int c = 0; c < 8; c++) {
            CPASYNC16(sb + c*8192 + off,        gB + (size_t)c*8192 + off);
            CPASYNC16(sb + c*8192 + off + 4096, gB + (size_t)c*8192 + off + 4096);
        }
        CPCOMMIT();
    }

    int r15 = lane & 15, hi2 = lane >> 4;
    uint32_t aoff[2]; int asw[2];
    #pragma unroll
    for (int i = 0; i < 2; i++) {
        int mr = mwarp + i*16 + r15;
        aoff[i] = mr * 64; asw[i] = (mr >> 1) & 3;
    }
    uint32_t boff[4]; int bsw[4];
    #pragma unroll
    for (int j = 0; j < 4; j++) {
        int nr = nwarp + j*16 + r15;
        boff[j] = nr * 64; bsw[j] = (nr >> 1) & 3;
    }

    float d[2][8][4];
    #pragma unroll
    for (int i = 0; i < 2; i++)
        #pragma unroll
        for (int j = 0; j < 8; j++)
            #pragma unroll
            for (int q = 0; q < 4; q++) d[i][j][q] = 0.f;

    #define ISSUEG(g) do { \
        int _c = (g) & 7; \
        int _tile = (bid + (((g) >> 3) * NSM2)) >> 1; \
        size_t _ab = (size_t)_tile * 65536 + (size_t)_c * 8192; \
        uint32_t so = sb + 65536 + (uint32_t)((g) & 3) * ASTAGE; \
        uint32_t off = (uint32_t)tid * 16; \
        CPASYNC16(so + off,        gA + _ab + off); \
        CPASYNC16(so + off + 4096, gA + _ab + off + 4096); \
        CPCOMMIT(); \
    } while (0)

    ISSUEG(0);
    if (total > 1) ISSUEG(1);
    if (total > 2) ISSUEG(2);
    for (int g = 0; g < total; g++) {
        int rem = total - g - 1;
        if (rem >= 2)      { CPWAIT(2); }
        else if (rem == 1) { CPWAIT(1); }
        else               { CPWAIT(0); }
        __syncthreads();
        int c = g & 7;
        uint32_t abase = sb + 65536 + (uint32_t)(g & 3) * ASTAGE;
        uint32_t bbase = sb + (uint32_t)c * 8192;
        #pragma unroll
        for (int s = 0; s < 2; s++) {
            uint32_t ah[2][4];
            #pragma unroll
            for (int i = 0; i < 2; i++) {
                uint32_t kc = (uint32_t)((((s<<1)|hi2) ^ asw[i]) << 4);
                LDSM4(ah[i][0],ah[i][1],ah[i][2],ah[i][3], abase + aoff[i] + kc);
            }
            #pragma unroll
            for (int jp = 0; jp < 2; jp++) {
                uint32_t bf[2][4];
                #pragma unroll
                for (int q = 0; q < 2; q++) {
                    int j = jp*2 + q;
                    uint32_t kc = (uint32_t)((((s<<1)|hi2) ^ bsw[j]) << 4);
                    LDSM4(bf[q][0],bf[q][1],bf[q][2],bf[q][3], bbase + boff[j] + kc);
                }
                #pragma unroll
                for (int q = 0; q < 2; q++)
                    #pragma unroll
                    for (int i = 0; i < 2; i++) {
                        MMA16816(d[i][4*jp+2*q],   ah[i], bf[q][0], bf[q][2]);
                        MMA16816(d[i][4*jp+2*q+1], ah[i], bf[q][1], bf[q][3]);
                    }
            }
        }
        if (g + 3 < total) ISSUEG(g+3);
        if (c == 7) {
            // epilogue: write plain row-major fp16 (overlaps in-flight loads)
            int tile = (bid + ((g >> 3) * NSM2)) >> 1;
            int rr = lane >> 2, cp = (lane & 3) * 2;
            #pragma unroll
            for (int i = 0; i < 2; i++) {
                size_t row = (size_t)tile*128 + mwarp + i*16 + rr;
                #pragma unroll
                for (int j = 0; j < 8; j++) {
                    int col = nh*128 + nwarp + j*8 + cp;
                    __half2 v01 = __floats2half2_rn(d[i][j][0], d[i][j][1]);
                    __half2 v23 = __floats2half2_rn(d[i][j][2], d[i][j][3]);
                    *(__half2*)(Hp + row*CC + col)       = v01;
                    *(__half2*)(Hp + (row+8)*CC + col)   = v23;
                }
            }
            #pragma unroll
            for (int i = 0; i < 2; i++)
                #pragma unroll
                for (int j = 0; j < 8; j++)
                    #pragma unroll
                    for (int q = 0; q < 4; q++) d[i][j][q] = 0.f;
        }
    }
}

// ---------------- aggregation (plain fp16 in; HFMA2 accumulation) ----------------
// acc = sum_in-edges norm*h[b,src,:] + dinv^2*h[b,n,:]  (fp16 half2 accum)
// then fp32: + bias (+res), relu; out to fp16 image or fp32.
__global__ __launch_bounds__(256) void k_agg(const __half* __restrict__ Hp, int set,
                                             const float* __restrict__ bias,
                                             const float* __restrict__ residual,
                                             float* __restrict__ out,
                                             __half* __restrict__ Aimg) {
    int g    = threadIdx.x >> 5;           // batch sub-group 0..7
    int lane = threadIdx.x & 31;           // channel/8
    int n = blockIdx.x;
    int b = blockIdx.y * 8 + g;
    int ch = lane * 8;

    const int* ptr = g_ptr + set*(NN+1);
    int p0 = __ldg(&ptr[n]), p1 = __ldg(&ptr[n+1]);
    float dn = __ldg(&g_dinv[set*NN + n]);
    int bbase = b * NN;
    int m = bbase + n;
    const __half* Hb = Hp + (size_t)bbase * CC + ch;

    // self term in half2
    uint4 pks = *(const uint4*)(Hp + (size_t)m * CC + ch);
    __half2 ws = __float2half2_rn(dn * dn);
    __half2 hacc[4];
    hacc[0] = __hmul2(*(__half2*)&pks.x, ws);
    hacc[1] = __hmul2(*(__half2*)&pks.y, ws);
    hacc[2] = __hmul2(*(__half2*)&pks.z, ws);
    hacc[3] = __hmul2(*(__half2*)&pks.w, ws);

    int off = set*MAXE;
    int j = p0;
    for (; j + 4 <= p1; j += 4) {
        int s0 = __ldg(&g_esrc[off + j]);
        int s1 = __ldg(&g_esrc[off + j + 1]);
        int s2 = __ldg(&g_esrc[off + j + 2]);
        int s3 = __ldg(&g_esrc[off + j + 3]);
        uint32_t w0r = __ldg(&g_enorm2[off + j]);
        uint32_t w1r = __ldg(&g_enorm2[off + j + 1]);
        uint32_t w2r = __ldg(&g_enorm2[off + j + 2]);
        uint32_t w3r = __ldg(&g_enorm2[off + j + 3]);
        uint4 pk0 = *(const uint4*)(Hb + (size_t)s0 * CC);
        uint4 pk1 = *(const uint4*)(Hb + (size_t)s1 * CC);
        uint4 pk2 = *(const uint4*)(Hb + (size_t)s2 * CC);
        uint4 pk3 = *(const uint4*)(Hb + (size_t)s3 * CC);
        __half2 w0 = *(__half2*)&w0r, w1 = *(__half2*)&w1r;
        __half2 w2 = *(__half2*)&w2r, w3 = *(__half2*)&w3r;
        hacc[0] = __hfma2(*(__half2*)&pk0.x, w0, hacc[0]);
        hacc[1] = __hfma2(*(__half2*)&pk0.y, w0, hacc[1]);
        hacc[2] = __hfma2(*(__half2*)&pk0.z, w0, hacc[2]);
        hacc[3] = __hfma2(*(__half2*)&pk0.w, w0, hacc[3]);
        hacc[0] = __hfma2(*(__half2*)&pk1.x, w1, hacc[0]);
        hacc[1] = __hfma2(*(__half2*)&pk1.y, w1, hacc[1]);
        hacc[2] = __hfma2(*(__half2*)&pk1.z, w1, hacc[2]);
        hacc[3] = __hfma2(*(__half2*)&pk1.w, w1, hacc[3]);
        hacc[0] = __hfma2(*(__half2*)&pk2.x, w2, hacc[0]);
        hacc[1] = __hfma2(*(__half2*)&pk2.y, w2, hacc[1]);
        hacc[2] = __hfma2(*(__half2*)&pk2.z, w2, hacc[2]);
        hacc[3] = __hfma2(*(__half2*)&pk2.w, w2, hacc[3]);
        hacc[0] = __hfma2(*(__half2*)&pk3.x, w3, hacc[0]);
        hacc[1] = __hfma2(*(__half2*)&pk3.y, w3, hacc[1]);
        hacc[2] = __hfma2(*(__half2*)&pk3.z, w3, hacc[2]);
        hacc[3] = __hfma2(*(__half2*)&pk3.w, w3, hacc[3]);
    }
    for (; j < p1; ++j) {
        int s0 = __ldg(&g_esrc[off + j]);
        uint32_t w0r = __ldg(&g_enorm2[off + j]);
        uint4 pk0 = *(const uint4*)(Hb + (size_t)s0 * CC);
        __half2 w0 = *(__half2*)&w0r;
        hacc[0] = __hfma2(*(__half2*)&pk0.x, w0, hacc[0]);
        hacc[1] = __hfma2(*(__half2*)&pk0.y, w0, hacc[1]);
        hacc[2] = __hfma2(*(__half2*)&pk0.z, w0, hacc[2]);
        hacc[3] = __hfma2(*(__half2*)&pk0.w, w0, hacc[3]);
    }

    // finish in fp32
    float acc[8];
    float2 f0 = __half22float2(hacc[0]);
    float2 f1 = __half22float2(hacc[1]);
    float2 f2 = __half22float2(hacc[2]);
    float2 f3 = __half22float2(hacc[3]);
    acc[0]=f0.x; acc[1]=f0.y; acc[2]=f1.x; acc[3]=f1.y;
    acc[4]=f2.x; acc[5]=f2.y; acc[6]=f3.x; acc[7]=f3.y;

    float4 bi0 = *(const float4*)&bias[ch];
    float4 bi1 = *(const float4*)&bias[ch + 4];
    acc[0]+=bi0.x; acc[1]+=bi0.y; acc[2]+=bi0.z; acc[3]+=bi0.w;
    acc[4]+=bi1.x; acc[5]+=bi1.y; acc[6]+=bi1.z; acc[7]+=bi1.w;
    if (residual) {
        size_t rb = (size_t)m * CC + ch;
        float4 r0 = *(const float4*)&residual[rb];
        float4 r1 = *(const float4*)&residual[rb + 4];
        acc[0]+=r0.x; acc[1]+=r0.y; acc[2]+=r0.z; acc[3]+=r0.w;
        acc[4]+=r1.x; acc[5]+=r1.y; acc[6]+=r1.z; acc[7]+=r1.w;
    }
    #pragma unroll
    for (int e = 0; e < 8; e++) acc[e] = fmaxf(acc[e], 0.f);

    if (Aimg) {
        *(uint4*)(Aimg + img_off(m, ch)) = pack8h(acc);
    } else {
        size_t ob = (size_t)m * CC + ch;
        *(float4*)&out[ob]     = make_float4(acc[0], acc[1], acc[2], acc[3]);
        *(float4*)&out[ob + 4] = make_float4(acc[4], acc[5], acc[6], acc[7]);
    }
}

// ---------------- launch ----------------
extern "C" void kernel_launch(void* const* d_in, const int* in_sizes, int n_in,
                              void* d_out, int out_size) {
    const float* x  = (const float*)d_in[0];
    const float* W1 = (const float*)d_in[1];
    const float* b1 = (const float*)d_in[2];
    const float* W2 = (const float*)d_in[3];
    const float* b2 = (const float*)d_in[4];
    const float* W3 = (const float*)d_in[5];
    const float* b3 = (const float*)d_in[6];
    const int*   sp = (const int*)d_in[7];
    const int*   tm = (const int*)d_in[8];
    int Esp = in_sizes[7] / 2;
    int Etm = in_sizes[8] / 2;
    float* out = (float*)d_out;

    __half *ax, *hx, *bh;
    cudaGetSymbolAddress((void**)&ax, g_ax);
    cudaGetSymbolAddress((void**)&hx, g_hx);
    cudaGetSymbolAddress((void**)&bh, g_bh);

    cudaFuncSetAttribute(k_gemm_mma, cudaFuncAttributeMaxDynamicSharedMemorySize, GSM);

    dim3 ga(NN, BB/8);                // (1700, 8)

    // launches: conv(1), prep(2), gemm1(3), agg1(4) — slot 4 profiled => k_agg
    k_conv<<<CONVA_BLOCKS + 192, 256>>>(x, W1, W2, W3);
    k_prep<<<2, 1024>>>(sp, Esp, tm, Etm);

    // conv1
    k_gemm_mma<<<NSM2, 256, GSM>>>(ax, bh, hx);
    k_agg<<<ga, 256>>>(hx, 0, b1, nullptr, nullptr, ax);   // launch #4 — profiled
    // conv2
    k_gemm_mma<<<NSM2, 256, GSM>>>(ax, bh + 65536, hx);
    k_agg<<<ga, 256>>>(hx, 1, b2, nullptr, nullptr, ax);
    // conv3
    k_gemm_mma<<<NSM2, 256, GSM>>>(ax, bh + 2*65536, hx);
    k_agg<<<ga, 256>>>(hx, 0, b3, x, out, nullptr);
}

// round 17
// speedup vs baseline: 3.7990x; 1.0059x over previous
#include <cuda_runtime.h>
#include <cuda_fp16.h>
#include <cstdint>

typedef unsigned long long ull;

#define BB 64
#define NN 1700
#define CC 256
#define MAXE 16384
#define MTOT (BB*NN)
#define MTILES (MTOT/128)          // 850
#define NHT (MTILES*2)             // 1700 half-tiles (128x128)
#define NSM2 296                   // 2 CTAs per SM

// ---------------- scratch (device globals; no allocation allowed) ----------------
__device__ __half g_ax[(size_t)MTOT*CC];           // A input (fp16, PLAIN row-major, GEMM input)
__device__ __half g_hx[(size_t)MTOT*CC];           // H output (fp16, PLAIN row-major, agg input)
__device__ __half g_bh[3*65536];                   // B fp16 images per layer (swizzled)
__device__ int      g_ptr[2*(NN+1)];
__device__ float    g_dinv[2*NN];
__device__ int      g_esrc[2*MAXE];
__device__ uint32_t g_enorm2[2*MAXE];              // edge norms pre-packed as half2

// ---------------- PTX helpers (all sm_80-class: valid for compute_103) ----------------
__device__ __forceinline__ uint32_t smem_u32(const void* p) {
    uint32_t a;
    asm("{ .reg .u64 t; cvta.to.shared.u64 t, %1; cvt.u32.u64 %0, t; }" : "=r"(a) : "l"(p));
    return a;
}
#define LDSM4(r0,r1,r2,r3,addr) \
    asm volatile("ldmatrix.sync.aligned.m8n8.x4.shared.b16 {%0,%1,%2,%3}, [%4];" \
        : "=r"(r0),"=r"(r1),"=r"(r2),"=r"(r3) : "r"(addr))
#define MMA16816(d, a, b0, b1) \
    asm volatile("mma.sync.aligned.m16n8k16.row.col.f32.f16.f16.f32 " \
        "{%0,%1,%2,%3},{%4,%5,%6,%7},{%8,%9},{%0,%1,%2,%3};" \
        : "+f"((d)[0]),"+f"((d)[1]),"+f"((d)[2]),"+f"((d)[3]) \
        : "r"((a)[0]),"r"((a)[1]),"r"((a)[2]),"r"((a)[3]), "r"(b0),"r"(b1))
#define CPASYNC16(dst, src) \
    asm volatile("cp.async.cg.shared.global [%0], [%1], 16;" :: "r"(dst), "l"(src))
#define CPCOMMIT() asm volatile("cp.async.commit_group;")
#define CPWAIT(n)  asm volatile("cp.async.wait_group %0;" :: "n"(n))

// chunked image element offset within a 128x32 block (64B rows), 16B-chunk XOR swizzle
__device__ __forceinline__ uint32_t swz_elem(int r, int kin) {
    return (uint32_t)(r*32 + ((((kin>>3) ^ ((r>>1)&3)))<<3) + (kin&7));
}

// ---------------- parallel prep: one block per edge set ----------------
__global__ __launch_bounds__(1024) void k_prep(const int* __restrict__ sp, int Esp,
                                               const int* __restrict__ tm, int Etm) {
    __shared__ int   cnt[NN];
    __shared__ float dv [NN];
    __shared__ int   sbuf[2048];
    int set = blockIdx.x;
    const int* edges = (set == 0) ? sp : tm;
    int E = (set == 0) ? Esp : Etm;
    const int* erow = edges;
    const int* ecol = edges + E;
    int t = threadIdx.x;

    for (int i = t; i < NN; i += 1024) cnt[i] = 0;
    __syncthreads();
    for (int e = t; e < E; e += 1024) atomicAdd(&cnt[ecol[e]], 1);
    __syncthreads();
    for (int i = t; i < NN; i += 1024) {
        float d = rsqrtf((float)(cnt[i] + 1));     // +1 self loop
        dv[i] = d; g_dinv[set*NN + i] = d;
    }
    __syncthreads();
    for (int i = t; i < 2048; i += 1024) sbuf[i] = (i < NN) ? cnt[i] : 0;
    __syncthreads();
    for (int off = 1; off < 2048; off <<= 1) {
        int v0 = (t >= off) ? sbuf[t - off] : 0;
        int i1 = t + 1024;
        int v1 = sbuf[i1 - off];
        __syncthreads();
        sbuf[t] += v0; sbuf[i1] += v1;
        __syncthreads();
    }
    int* ptr = g_ptr + set*(NN+1);
    for (int i = t; i <= NN; i += 1024) ptr[i] = (i == 0) ? 0 : sbuf[i-1];
    __syncthreads();
    for (int i = t; i < NN; i += 1024) cnt[i] = 0;   // reuse as cursors
    __syncthreads();
    for (int e = t; e < E; e += 1024) {
        int r = erow[e], c = ecol[e];
        float nrm = dv[r] * dv[c];
        __half2 nh = __float2half2_rn(nrm);
        int pos = ptr[c] + atomicAdd(&cnt[c], 1);
        g_esrc  [set*MAXE + pos] = r;
        g_enorm2[set*MAXE + pos] = *(uint32_t*)&nh;
    }
}

// ---------------- pack helper ----------------
__device__ __forceinline__ uint4 pack8h(const float* v) {
    __half2 p0 = __floats2half2_rn(v[0], v[1]);
    __half2 p1 = __floats2half2_rn(v[2], v[3]);
    __half2 p2 = __floats2half2_rn(v[4], v[5]);
    __half2 p3 = __floats2half2_rn(v[6], v[7]);
    uint4 r;
    r.x = *(uint32_t*)&p0; r.y = *(uint32_t*)&p1;
    r.z = *(uint32_t*)&p2; r.w = *(uint32_t*)&p3;
    return r;
}

// fused conversion: blocks [0, 13600) convert X (plain); blocks [13600, 13792) convert W1/W2/W3
#define CONVA_BLOCKS (MTOT/8)      // 13600 (8 rows per 256-thr block)
__global__ __launch_bounds__(256) void k_conv(const float* __restrict__ X,
                                              const float* __restrict__ W1,
                                              const float* __restrict__ W2,
                                              const float* __restrict__ W3) {
    if (blockIdx.x < CONVA_BLOCKS) {
        int idx = blockIdx.x * 256 + threadIdx.x;
        int m = idx >> 5, lane = idx & 31;
        int ch = lane * 8;
        float v[8];
        *(float4*)&v[0] = *(const float4*)&X[(size_t)m * CC + ch];
        *(float4*)&v[4] = *(const float4*)&X[(size_t)m * CC + ch + 4];
        *(uint4*)(g_ax + (size_t)m * CC + ch) = pack8h(v);
    } else {
        int wb = blockIdx.x - CONVA_BLOCKS;        // 0..191
        int layer = wb >> 6;
        const float* W = (layer == 0) ? W1 : ((layer == 1) ? W2 : W3);
        int idx = (wb & 63) * 256 + threadIdx.x;
        int n = idx >> 6, kq = idx & 63;
        int k = kq * 4;
        __half2 pA = __floats2half2_rn(W[(size_t)(k+0)*CC + n], W[(size_t)(k+1)*CC + n]);
        __half2 pB = __floats2half2_rn(W[(size_t)(k+2)*CC + n], W[(size_t)(k+3)*CC + n]);
        uint2 pk; pk.x = *(uint32_t*)&pA; pk.y = *(uint32_t*)&pB;
        int nh = n >> 7, ni = n & 127, chunk = k >> 5, kin = k & 31;
        size_t eo = (size_t)layer*65536 + (size_t)(nh*8 + chunk)*4096 + swz_elem(ni, kin);
        *(uint2*)(g_bh + eo) = pk;
    }
}

// ---------------- persistent HMMA GEMM (2 CTAs/SM, B-resident): Hplain = Aplain @ W ----------------
// grid (296): CTA bid handles half-tiles bid, bid+296, ... (nh = bid&1 fixed).
// B for this nh (64KB, swizzled image) loaded ONCE into smem; A streams from PLAIN
// row-major global with swizzle applied at the cp.async destination (4 stages x 8KB).
#define ASTAGE 8192
#define GSM (65536 + 4*ASTAGE)
__global__ __launch_bounds__(256, 2) void k_gemm_mma(const __half* __restrict__ Ap,
                                                     const __half* __restrict__ Bimg,
                                                     __half* __restrict__ Hp) {
    extern __shared__ __align__(128) char smc[];
    uint32_t sb = smem_u32(smc);
    int tid = threadIdx.x, wid = tid >> 5, lane = tid & 31;
    int bid = blockIdx.x;
    int nh = bid & 1;
    int mwarp = (wid >> 1) * 32, nwarp = (wid & 1) * 64;

    int nht = (NHT - bid + NSM2 - 1) / NSM2;
    int total = nht * 8;

    const char* gA = (const char*)Ap;
    const char* gB = (const char*)Bimg + (size_t)nh * 8 * 8192;

    // prologue: load full B half (64KB) into smem (group 0)
    {
        uint32_t off = (uint32_t)tid * 16;
        #pragma unroll
        for (int c = 0; c < 8; c++) {
            CPASYNC16(sb + c*8192 + off,        gB + (size_t)c*8192 + off);
            CPASYNC16(sb + c*8192 + off + 4096, gB + (size_t)c*8192 + off + 4096);
        }
        CPCOMMIT();
    }

    // per-thread A-copy offsets (loop-invariant): 2 units of 16B per thread
    // unit u (0..511): row = u>>2 (0..127), k16 = u&3; plain src = row*512 + k16*16;
    // swizzled smem dst = row*64 + ((k16 ^ ((row>>1)&3))<<4)
    uint32_t asrc[2], adst[2];
    #pragma unroll
    for (int q = 0; q < 2; q++) {
        int u = tid + q*256;
        int row = u >> 2, k16 = u & 3;
        asrc[q] = (uint32_t)(row*512 + k16*16);
        adst[q] = (uint32_t)(row*64 + ((k16 ^ ((row>>1)&3)) << 4));
    }

    int r15 = lane & 15, hi2 = lane >> 4;
    uint32_t aoff[2]; int asw[2];
    #pragma unroll
    for (int i = 0; i < 2; i++) {
        int mr = mwarp + i*16 + r15;
        aoff[i] = mr * 64; asw[i] = (mr >> 1) & 3;
    }
    uint32_t boff[4]; int bsw[4];
    #pragma unroll
    for (int j = 0; j < 4; j++) {
        int nr = nwarp + j*16 + r15;
        boff[j] = nr * 64; bsw[j] = (nr >> 1) & 3;
    }

    float d[2][8][4];
    #pragma unroll
    for (int i = 0; i < 2; i++)
        #pragma unroll
        for (int j = 0; j < 8; j++)
            #pragma unroll
            for (int q = 0; q < 4; q++) d[i][j][q] = 0.f;

    // issue A chunk g: tile rows [tile*128, +128), chs [c*32, +32), from PLAIN layout
    #define ISSUEG(g) do { \
        int _c = (g) & 7; \
        int _tile = (bid + (((g) >> 3) * NSM2)) >> 1; \
        const char* _src = gA + (size_t)_tile * 65536 + (uint32_t)(_c * 64); \
        uint32_t so = sb + 65536 + (uint32_t)((g) & 3) * ASTAGE; \
        CPASYNC16(so + adst[0], _src + asrc[0]); \
        CPASYNC16(so + adst[1], _src + asrc[1]); \
        CPCOMMIT(); \
    } while (0)

    ISSUEG(0);
    if (total > 1) ISSUEG(1);
    if (total > 2) ISSUEG(2);
    for (int g = 0; g < total; g++) {
        int rem = total - g - 1;
        if (rem >= 2)      { CPWAIT(2); }
        else if (rem == 1) { CPWAIT(1); }
        else               { CPWAIT(0); }
        __syncthreads();
        int c = g & 7;
        uint32_t abase = sb + 65536 + (uint32_t)(g & 3) * ASTAGE;
        uint32_t bbase = sb + (uint32_t)c * 8192;
        #pragma unroll
        for (int s = 0; s < 2; s++) {
            uint32_t ah[2][4];
            #pragma unroll
            for (int i = 0; i < 2; i++) {
                uint32_t kc = (uint32_t)((((s<<1)|hi2) ^ asw[i]) << 4);
                LDSM4(ah[i][0],ah[i][1],ah[i][2],ah[i][3], abase + aoff[i] + kc);
            }
            #pragma unroll
            for (int jp = 0; jp < 2; jp++) {
                uint32_t bf[2][4];
                #pragma unroll
                for (int q = 0; q < 2; q++) {
                    int j = jp*2 + q;
                    uint32_t kc = (uint32_t)((((s<<1)|hi2) ^ bsw[j]) << 4);
                    LDSM4(bf[q][0],bf[q][1],bf[q][2],bf[q][3], bbase + boff[j] + kc);
                }
                #pragma unroll
                for (int q = 0; q < 2; q++)
                    #pragma unroll
                    for (int i = 0; i < 2; i++) {
                        MMA16816(d[i][4*jp+2*q],   ah[i], bf[q][0], bf[q][2]);
                        MMA16816(d[i][4*jp+2*q+1], ah[i], bf[q][1], bf[q][3]);
                    }
            }
        }
        if (g + 3 < total) ISSUEG(g+3);
        if (c == 7) {
            // epilogue: write plain row-major fp16 (overlaps in-flight loads)
            int tile = (bid + ((g >> 3) * NSM2)) >> 1;
            int rr = lane >> 2, cp = (lane & 3) * 2;
            #pragma unroll
            for (int i = 0; i < 2; i++) {
                size_t row = (size_t)tile*128 + mwarp + i*16 + rr;
                #pragma unroll
                for (int j = 0; j < 8; j++) {
                    int col = nh*128 + nwarp + j*8 + cp;
                    __half2 v01 = __floats2half2_rn(d[i][j][0], d[i][j][1]);
                    __half2 v23 = __floats2half2_rn(d[i][j][2], d[i][j][3]);
                    *(__half2*)(Hp + row*CC + col)       = v01;
                    *(__half2*)(Hp + (row+8)*CC + col)   = v23;
                }
            }
            #pragma unroll
            for (int i = 0; i < 2; i++)
                #pragma unroll
                for (int j = 0; j < 8; j++)
                    #pragma unroll
                    for (int q = 0; q < 4; q++) d[i][j][q] = 0.f;
        }
    }
}

// ---------------- aggregation (plain fp16 in; HFMA2 accumulation; plain fp16/fp32 out) ----------------
__global__ __launch_bounds__(256) void k_agg(const __half* __restrict__ Hp, int set,
                                             const float* __restrict__ bias,
                                             const float* __restrict__ residual,
                                             float* __restrict__ out,
                                             __half* __restrict__ Ap) {
    int g    = threadIdx.x >> 5;           // batch sub-group 0..7
    int lane = threadIdx.x & 31;           // channel/8
    int n = blockIdx.x;
    int b = blockIdx.y * 8 + g;
    int ch = lane * 8;

    const int* ptr = g_ptr + set*(NN+1);
    int p0 = __ldg(&ptr[n]), p1 = __ldg(&ptr[n+1]);
    float dn = __ldg(&g_dinv[set*NN + n]);
    int bbase = b * NN;
    int m = bbase + n;
    const __half* Hb = Hp + (size_t)bbase * CC + ch;

    // self term in half2
    uint4 pks = *(const uint4*)(Hp + (size_t)m * CC + ch);
    __half2 ws = __float2half2_rn(dn * dn);
    __half2 hacc[4];
    hacc[0] = __hmul2(*(__half2*)&pks.x, ws);
    hacc[1] = __hmul2(*(__half2*)&pks.y, ws);
    hacc[2] = __hmul2(*(__half2*)&pks.z, ws);
    hacc[3] = __hmul2(*(__half2*)&pks.w, ws);

    int off = set*MAXE;
    int j = p0;
    for (; j + 4 <= p1; j += 4) {
        int s0 = __ldg(&g_esrc[off + j]);
        int s1 = __ldg(&g_esrc[off + j + 1]);
        int s2 = __ldg(&g_esrc[off + j + 2]);
        int s3 = __ldg(&g_esrc[off + j + 3]);
        uint32_t w0r = __ldg(&g_enorm2[off + j]);
        uint32_t w1r = __ldg(&g_enorm2[off + j + 1]);
        uint32_t w2r = __ldg(&g_enorm2[off + j + 2]);
        uint32_t w3r = __ldg(&g_enorm2[off + j + 3]);
        uint4 pk0 = *(const uint4*)(Hb + (size_t)s0 * CC);
        uint4 pk1 = *(const uint4*)(Hb + (size_t)s1 * CC);
        uint4 pk2 = *(const uint4*)(Hb + (size_t)s2 * CC);
        uint4 pk3 = *(const uint4*)(Hb + (size_t)s3 * CC);
        __half2 w0 = *(__half2*)&w0r, w1 = *(__half2*)&w1r;
        __half2 w2 = *(__half2*)&w2r, w3 = *(__half2*)&w3r;
        hacc[0] = __hfma2(*(__half2*)&pk0.x, w0, hacc[0]);
        hacc[1] = __hfma2(*(__half2*)&pk0.y, w0, hacc[1]);
        hacc[2] = __hfma2(*(__half2*)&pk0.z, w0, hacc[2]);
        hacc[3] = __hfma2(*(__half2*)&pk0.w, w0, hacc[3]);
        hacc[0] = __hfma2(*(__half2*)&pk1.x, w1, hacc[0]);
        hacc[1] = __hfma2(*(__half2*)&pk1.y, w1, hacc[1]);
        hacc[2] = __hfma2(*(__half2*)&pk1.z, w1, hacc[2]);
        hacc[3] = __hfma2(*(__half2*)&pk1.w, w1, hacc[3]);
        hacc[0] = __hfma2(*(__half2*)&pk2.x, w2, hacc[0]);
        hacc[1] = __hfma2(*(__half2*)&pk2.y, w2, hacc[1]);
        hacc[2] = __hfma2(*(__half2*)&pk2.z, w2, hacc[2]);
        hacc[3] = __hfma2(*(__half2*)&pk2.w, w2, hacc[3]);
        hacc[0] = __hfma2(*(__half2*)&pk3.x, w3, hacc[0]);
        hacc[1] = __hfma2(*(__half2*)&pk3.y, w3, hacc[1]);
        hacc[2] = __hfma2(*(__half2*)&pk3.z, w3, hacc[2]);
        hacc[3] = __hfma2(*(__half2*)&pk3.w, w3, hacc[3]);
    }
    for (; j < p1; ++j) {
        int s0 = __ldg(&g_esrc[off + j]);
        uint32_t w0r = __ldg(&g_enorm2[off + j]);
        uint4 pk0 = *(const uint4*)(Hb + (size_t)s0 * CC);
        __half2 w0 = *(__half2*)&w0r;
        hacc[0] = __hfma2(*(__half2*)&pk0.x, w0, hacc[0]);
        hacc[1] = __hfma2(*(__half2*)&pk0.y, w0, hacc[1]);
        hacc[2] = __hfma2(*(__half2*)&pk0.z, w0, hacc[2]);
        hacc[3] = __hfma2(*(__half2*)&pk0.w, w0, hacc[3]);
    }

    // finish in fp32
    float acc[8];
    float2 f0 = __half22float2(hacc[0]);
    float2 f1 = __half22float2(hacc[1]);
    float2 f2 = __half22float2(hacc[2]);
    float2 f3 = __half22float2(hacc[3]);
    acc[0]=f0.x; acc[1]=f0.y; acc[2]=f1.x; acc[3]=f1.y;
    acc[4]=f2.x; acc[5]=f2.y; acc[6]=f3.x; acc[7]=f3.y;

    float4 bi0 = *(const float4*)&bias[ch];
    float4 bi1 = *(const float4*)&bias[ch + 4];
    acc[0]+=bi0.x; acc[1]+=bi0.y; acc[2]+=bi0.z; acc[3]+=bi0.w;
    acc[4]+=bi1.x; acc[5]+=bi1.y; acc[6]+=bi1.z; acc[7]+=bi1.w;
    if (residual) {
        size_t rb = (size_t)m * CC + ch;
        float4 r0 = *(const float4*)&residual[rb];
        float4 r1 = *(const float4*)&residual[rb + 4];
        acc[0]+=r0.x; acc[1]+=r0.y; acc[2]+=r0.z; acc[3]+=r0.w;
        acc[4]+=r1.x; acc[5]+=r1.y; acc[6]+=r1.z; acc[7]+=r1.w;
    }
    #pragma unroll
    for (int e = 0; e < 8; e++) acc[e] = fmaxf(acc[e], 0.f);

    if (Ap) {
        *(uint4*)(Ap + (size_t)m * CC + ch) = pack8h(acc);   // plain coalesced
    } else {
        size_t ob = (size_t)m * CC + ch;
        *(float4*)&out[ob]     = make_float4(acc[0], acc[1], acc[2], acc[3]);
        *(float4*)&out[ob + 4] = make_float4(acc[4], acc[5], acc[6], acc[7]);
    }
}

// ---------------- launch ----------------
extern "C" void kernel_launch(void* const* d_in, const int* in_sizes, int n_in,
                              void* d_out, int out_size) {
    const float* x  = (const float*)d_in[0];
    const float* W1 = (const float*)d_in[1];
    const float* b1 = (const float*)d_in[2];
    const float* W2 = (const float*)d_in[3];
    const float* b2 = (const float*)d_in[4];
    const float* W3 = (const float*)d_in[5];
    const float* b3 = (const float*)d_in[6];
    const int*   sp = (const int*)d_in[7];
    const int*   tm = (const int*)d_in[8];
    int Esp = in_sizes[7] / 2;
    int Etm = in_sizes[8] / 2;
    float* out = (float*)d_out;

    __half *ax, *hx, *bh;
    cudaGetSymbolAddress((void**)&ax, g_ax);
    cudaGetSymbolAddress((void**)&hx, g_hx);
    cudaGetSymbolAddress((void**)&bh, g_bh);

    cudaFuncSetAttribute(k_gemm_mma, cudaFuncAttributeMaxDynamicSharedMemorySize, GSM);

    dim3 ga(NN, BB/8);                // (1700, 8)

    // launches: conv(1), prep(2), gemm1(3), agg1(4) — slot 4 profiled => k_agg
    k_conv<<<CONVA_BLOCKS + 192, 256>>>(x, W1, W2, W3);
    k_prep<<<2, 1024>>>(sp, Esp, tm, Etm);

    // conv1
    k_gemm_mma<<<NSM2, 256, GSM>>>(ax, bh, hx);
    k_agg<<<ga, 256>>>(hx, 0, b1, nullptr, nullptr, ax);   // launch #4 — profiled
    // conv2
    k_gemm_mma<<<NSM2, 256, GSM>>>(ax, bh + 65536, hx);
    k_agg<<<ga, 256>>>(hx, 1, b2, nullptr, nullptr, ax);
    // conv3
    k_gemm_mma<<<NSM2, 256, GSM>>>(ax, bh + 2*65536, hx);
    k_agg<<<ga, 256>>>(hx, 0, b3, x, out, nullptr);
}